// round 14
// baseline (speedup 1.0000x reference)
#include <cuda_runtime.h>
#include <cuda_fp16.h>
#include <cstdint>

#define BB   8
#define LL   1024
#define DDIM 512
#define HH   8
#define EE   64
#define DFF  2048
#define NBLK 3
#define NQKV 1536
#define BLD  (BB*LL*DDIM)
#define BLQ  (BB*LL*NQKV)
#define BLL  (BB*LL*LL)
#define BHLL (BB*HH*LL*LL)
#define BLDF (BB*LL*DFF)
#define DD2  (DDIM*DDIM)

// ---------------- fp32 scratch ----------------
__device__ float g_t[BLD];
__device__ float g_t2[BLD];
__device__ float g_x[BLD];
__device__ float g_y[BLD];
__device__ float g_s[BLL];
__device__ float g_A[BHLL];
__device__ float g_qkvb[NQKV];
__device__ float g_tqkvb[NBLK*NQKV];
// ---------------- half hi/lo scratch ----------------
__device__ __half g_x0h[BLD],  g_x0l[BLD];
__device__ __half g_qkvh[BLQ], g_qkvl[BLQ];
__device__ __half g_vth[BLD],  g_vtl[BLD];
__device__ __half g_th[BLD],   g_tl[BLD];
__device__ __half g_t2h[BLD],  g_t2l[BLD];
__device__ __half g_yh[BLD],   g_yl[BLD];
__device__ __half g_xnh[BLD],  g_xnl[BLD];
__device__ __half g_hh[BLDF],  g_hl[BLDF];
__device__ __half g_sh[BLL],   g_sl[BLL];     // temporal probs halves only
__device__ __half g_awqkvh[3*DD2], g_awqkvl[3*DD2];
__device__ __half g_awoh[DD2],     g_awol[DD2];
__device__ __half g_tqkvwh[NBLK*3*DD2], g_tqkvwl[NBLK*3*DD2];
__device__ __half g_towh[NBLK*DD2],     g_towl[NBLK*DD2];
__device__ __half g_f1h[NBLK*DDIM*DFF], g_f1l[NBLK*DDIM*DFF];
__device__ __half g_f2h[NBLK*DFF*DDIM], g_f2l[NBLK*DFF*DDIM];

// ---------------- helpers ----------------
#define SWZ(o) ((uint32_t)(o) ^ ((((uint32_t)(o)) >> 3) & 0x70u))

__device__ __forceinline__ void mma16816(float* d, const uint32_t* a, uint32_t b0, uint32_t b1) {
    asm volatile(
        "mma.sync.aligned.m16n8k16.row.col.f32.f16.f16.f32 "
        "{%0,%1,%2,%3}, {%4,%5,%6,%7}, {%8,%9}, {%0,%1,%2,%3};"
        : "+f"(d[0]), "+f"(d[1]), "+f"(d[2]), "+f"(d[3])
        : "r"(a[0]), "r"(a[1]), "r"(a[2]), "r"(a[3]), "r"(b0), "r"(b1));
}
__device__ __forceinline__ void ldm_x4(uint32_t* r, uint32_t addr) {
    asm volatile("ldmatrix.sync.aligned.m8n8.x4.shared.b16 {%0,%1,%2,%3}, [%4];"
        : "=r"(r[0]), "=r"(r[1]), "=r"(r[2]), "=r"(r[3]) : "r"(addr));
}
__device__ __forceinline__ void cp16(uint32_t dst, const void* src) {
    asm volatile("cp.async.cg.shared.global [%0], [%1], 16;" :: "r"(dst), "l"(src));
}
#define CP_COMMIT() asm volatile("cp.async.commit_group;" ::: "memory")
#define CP_WAIT1()  asm volatile("cp.async.wait_group 1;" ::: "memory")

__device__ __forceinline__ void split2(float x, float y, __half2& h, __half2& l) {
    h = __floats2half2_rn(x, y);
    float2 f = __half22float2(h);
    l = __floats2half2_rn(x - f.x, y - f.y);
}

// ============ fp16 hi/lo split tensor GEMM (3-term, fp32-grade) ============
// C = alpha*A@B^T (+bias)(+res)(relu).
// SPLITA=false: A given as hi/lo half arrays (cp.async path).
// SPLITA=true : A given as fp32 (Af); register-staged LDG -> split -> STS.
// CTA 128xBN, 256 threads = 8 warps, warp tile 32x(BN/2). 3-stage pipeline, 2 CTAs/SM.
template<int BN, bool RELU, bool SPLITA>
__global__ void __launch_bounds__(256, 2) hgemm(
    const __half* __restrict__ Ah, const __half* __restrict__ Al,
    const float* __restrict__ Af,
    const __half* __restrict__ Bh, const __half* __restrict__ Bl,
    float* __restrict__ C, __half* __restrict__ Ch, __half* __restrict__ Cl,
    const float* __restrict__ bias, const float* __restrict__ res,
    int K, int lda, int ldb, int ldc, float alpha, int inner,
    long long sAo, long long sAi, long long sBo, long long sBi,
    long long sCo, long long sCi)
{
    constexpr int NA   = BN / 16;
    constexpr int ABYT = 128 * 128;
    constexpr int BBYT = BN * 128;
    constexpr int STG  = ABYT + BBYT;
    constexpr int AIT  = 4;
    constexpr int BIT  = BN * 8 / 256;

    extern __shared__ char smch[];
    const uint32_t smb0 = (uint32_t)__cvta_generic_to_shared(smch);

    int z  = blockIdx.z;
    int zo = z / inner;
    int zi = z - zo * inner;
    if (SPLITA) { Af += zo * sAo + zi * sAi; }
    else        { Ah += zo * sAo + zi * sAi;  Al += zo * sAo + zi * sAi; }
    Bh += zo * sBo + zi * sBi;  Bl += zo * sBo + zi * sBi;
    long long coff = zo * sCo + zi * sCi;
    if (C)  C  += coff;
    if (Ch) { Ch += coff; Cl += coff; }
    if (res) res += coff;

    const int tid  = threadIdx.x;
    const int wid  = tid >> 5, lane = tid & 31;
    const int g    = lane >> 2, t4 = lane & 3;
    const int row0 = blockIdx.y * 128, col0 = blockIdx.x * BN;
    const int arow = (wid & 3) * 32;
    const int brow = (wid >> 2) * (BN / 2);

    const int a_r   = arow + (lane & 15);
    const int a_q   = lane >> 4;
    const int b_mat = lane >> 3, b_row = lane & 7;
    const int b_n   = brow + (b_mat >> 1) * 8 + b_row;
    const int b_q   = b_mat & 1;

    float acc[2][NA][4];
    #pragma unroll
    for (int i = 0; i < 2; i++)
        #pragma unroll
        for (int j = 0; j < NA; j++)
            #pragma unroll
            for (int e = 0; e < 4; e++) acc[i][j][e] = 0.f;

    const int NC = K >> 5;

    float4 areg[4];
    auto ldgA = [&](int c) {
        if (SPLITA && c < NC) {
            const int k0 = c << 5;
            #pragma unroll
            for (int i = 0; i < 4; i++) {
                int cb = tid + i * 256;
                int r = cb >> 3, q = cb & 7;   // 8 float4 per 32-float row
                areg[i] = *(const float4*)(Af + (size_t)(row0 + r) * lda + k0 + q * 4);
            }
        }
    };
    auto stsA = [&](int c, int st) {
        if (SPLITA && c < NC) {
            char* base = smch + st * STG;
            #pragma unroll
            for (int i = 0; i < 4; i++) {
                int cb = tid + i * 256;
                int r = cb >> 3, q = cb & 7;
                __half2 h0, l0, h1, l1;
                split2(areg[i].x, areg[i].y, h0, l0);
                split2(areg[i].z, areg[i].w, h1, l1);
                uint2 hv = make_uint2(*(uint32_t*)&h0, *(uint32_t*)&h1);
                uint2 lv = make_uint2(*(uint32_t*)&l0, *(uint32_t*)&l1);
                *(uint2*)(base + SWZ(r * 128 + q * 8))      = hv;
                *(uint2*)(base + SWZ(r * 128 + 64 + q * 8)) = lv;
            }
        }
    };

    auto issue_stage = [&](int c, int st) {
        if (c < NC) {
            const int k0 = c << 5;
            uint32_t sA = smb0 + st * STG;
            uint32_t sB = sA + ABYT;
            if (!SPLITA) {
                #pragma unroll
                for (int i = 0; i < AIT; i++) {
                    int cb = tid + i * 256;
                    int r = cb >> 3, sub = cb & 7;
                    const __half* src = (sub < 4 ? Ah : Al) + (size_t)(row0 + r) * lda + k0 + (sub & 3) * 8;
                    cp16(sA + SWZ(r * 128 + sub * 16), src);
                }
            }
            #pragma unroll
            for (int i = 0; i < BIT; i++) {
                int cb = tid + i * 256;
                int r = cb >> 3, sub = cb & 7;
                const __half* src = (sub < 4 ? Bh : Bl) + (size_t)(col0 + r) * ldb + k0 + (sub & 3) * 8;
                cp16(sB + SWZ(r * 128 + sub * 16), src);
            }
        }
        CP_COMMIT();
    };

    // prologue
    if (SPLITA) { ldgA(0); stsA(0, 0); ldgA(1); stsA(1, 1); }
    issue_stage(0, 0);
    issue_stage(1, 1);

    for (int c = 0; c < NC; c++) {
        ldgA(c + 2);                     // overlap LDG with cp.async wait
        CP_WAIT1();
        __syncthreads();                 // stage (c-1)%3 now free
        issue_stage(c + 2, (c + 2) % 3);
        stsA(c + 2, (c + 2) % 3);

        const uint32_t sA = smb0 + (c % 3) * STG;
        const uint32_t sB = sA + ABYT;

        #pragma unroll
        for (int ka = 0; ka < 2; ka++) {
            uint32_t ah[2][4], al[2][4];
            #pragma unroll
            for (int ma = 0; ma < 2; ma++) {
                uint32_t off = (uint32_t)(a_r + ma * 16) * 128u + (uint32_t)(ka * 2 + a_q) * 16u;
                ldm_x4(ah[ma], sA + SWZ(off));
                ldm_x4(al[ma], sA + SWZ(off + 64));
            }
            #pragma unroll
            for (int p = 0; p < NA / 2; p++) {
                uint32_t off = (uint32_t)(b_n + p * 16) * 128u + (uint32_t)(ka * 2 + b_q) * 16u;
                uint32_t bh[4], bl[4];
                ldm_x4(bh, sB + SWZ(off));
                ldm_x4(bl, sB + SWZ(off + 64));
                #pragma unroll
                for (int e = 0; e < 2; e++) {
                    #pragma unroll
                    for (int ma = 0; ma < 2; ma++) {
                        float* ac = acc[ma][p * 2 + e];
                        mma16816(ac, ah[ma], bh[e * 2], bh[e * 2 + 1]);
                        mma16816(ac, ah[ma], bl[e * 2], bl[e * 2 + 1]);
                        mma16816(ac, al[ma], bh[e * 2], bh[e * 2 + 1]);
                    }
                }
            }
        }
        if (SPLITA) __syncthreads();     // protect stsA target from racing ldmatrix next iter
    }

    // ---- epilogue ----
    #pragma unroll
    for (int ma = 0; ma < 2; ma++) {
        #pragma unroll
        for (int na = 0; na < NA; na++) {
            int r_ = row0 + arow + ma * 16 + g;
            int n_ = col0 + brow + na * 8 + t4 * 2;
            float2 bb = bias ? *(const float2*)&bias[n_] : make_float2(0.f, 0.f);
            #pragma unroll
            for (int hf = 0; hf < 2; hf++) {
                int m = r_ + hf * 8;
                float2 v;
                v.x = acc[ma][na][hf * 2 + 0] * alpha + bb.x;
                v.y = acc[ma][na][hf * 2 + 1] * alpha + bb.y;
                if (res) {
                    float2 rr = *(const float2*)&res[(size_t)m * ldc + n_];
                    v.x += rr.x; v.y += rr.y;
                }
                if (RELU) { v.x = fmaxf(v.x, 0.f); v.y = fmaxf(v.y, 0.f); }
                if (C) *(float2*)&C[(size_t)m * ldc + n_] = v;
                if (Ch) {
                    __half2 h2, l2; split2(v.x, v.y, h2, l2);
                    *(__half2*)&Ch[(size_t)m * ldc + n_] = h2;
                    *(__half2*)&Cl[(size_t)m * ldc + n_] = l2;
                }
            }
        }
    }
}

// ---------------- transpose(+split) ----------------
__global__ void transpose_split_kernel(const float* __restrict__ in,
                                       __half* __restrict__ oh, __half* __restrict__ ol,
                                       int R, int C, long long in_bs, long long out_bs)
{
    __shared__ float tile[32][33];
    long long bi = (long long)blockIdx.z * in_bs;
    long long bo = (long long)blockIdx.z * out_bs;
    int c0 = blockIdx.x * 32, r0 = blockIdx.y * 32;
    int tx = threadIdx.x, ty = threadIdx.y;
    #pragma unroll
    for (int j = 0; j < 4; j++)
        tile[ty + j * 8][tx] = in[bi + (long long)(r0 + ty + j * 8) * C + c0 + tx];
    __syncthreads();
    #pragma unroll
    for (int j = 0; j < 4; j++) {
        float v = tile[tx][ty + j * 8];
        __half h = __float2half_rn(v);
        __half l = __float2half_rn(v - __half2float(h));
        long long idx = bo + (long long)(c0 + ty + j * 8) * R + r0 + tx;
        oh[idx] = h; ol[idx] = l;
    }
}

// ---------------- transpose passthrough of pre-split halves ----------------
__global__ void transpose_halves_kernel(const __half* __restrict__ inh, const __half* __restrict__ inl,
                                        int ldin, long long in_bs,
                                        __half* __restrict__ outh, __half* __restrict__ outl,
                                        int ldout, long long out_bs)
{
    __shared__ uint32_t tile[32][33];
    long long bi = (long long)blockIdx.z * in_bs;
    long long bo = (long long)blockIdx.z * out_bs;
    int c0 = blockIdx.x * 32, r0 = blockIdx.y * 32;
    int tx = threadIdx.x, ty = threadIdx.y;
    #pragma unroll
    for (int j = 0; j < 4; j++) {
        long long idx = bi + (long long)(r0 + ty + j * 8) * ldin + c0 + tx;
        uint32_t h = __half_as_ushort(inh[idx]);
        uint32_t l = __half_as_ushort(inl[idx]);
        tile[ty + j * 8][tx] = h | (l << 16);
    }
    __syncthreads();
    #pragma unroll
    for (int j = 0; j < 4; j++) {
        uint32_t u = tile[tx][ty + j * 8];
        long long idx = bo + (long long)(c0 + ty + j * 8) * ldout + r0 + tx;
        outh[idx] = __ushort_as_half((unsigned short)(u & 0xFFFFu));
        outl[idx] = __ushort_as_half((unsigned short)(u >> 16));
    }
}

// ---------------- elementwise split ----------------
__global__ void split_kernel(const float* __restrict__ in,
                             __half* __restrict__ oh, __half* __restrict__ ol, int n4)
{
    int i = blockIdx.x * 256 + threadIdx.x;
    if (i >= n4) return;
    float4 v = ((const float4*)in)[i];
    __half2 h01, l01, h23, l23;
    split2(v.x, v.y, h01, l01);
    split2(v.z, v.w, h23, l23);
    ((__half2*)oh)[i * 2] = h01; ((__half2*)oh)[i * 2 + 1] = h23;
    ((__half2*)ol)[i * 2] = l01; ((__half2*)ol)[i * 2 + 1] = l23;
}

// ---------------- bias packing ----------------
__global__ void bias_pack_kernel(const float* __restrict__ ab_q, const float* __restrict__ ab_k,
                                 const float* __restrict__ ab_v,
                                 const float* __restrict__ tqb, const float* __restrict__ tkb,
                                 const float* __restrict__ tvb,
                                 float* __restrict__ qkvb, float* __restrict__ tqkvb)
{
    int i = blockIdx.x * 256 + threadIdx.x;
    if (i < NQKV) {
        int sec = i >> 9, off = i & 511;
        qkvb[i] = (sec == 0 ? ab_q : sec == 1 ? ab_k : ab_v)[off];
        for (int b = 0; b < NBLK; b++) {
            const float* src = (sec == 0 ? tqb : sec == 1 ? tkb : tvb) + b * DDIM;
            tqkvb[b * NQKV + i] = src[off];
        }
    }
}

// ---------------- softmax rows of 1024; optional fp32 out; optional halves out ----------------
__global__ void softmax_kernel(const float* __restrict__ Pin, float* __restrict__ Pout,
                               __half* __restrict__ Ph, __half* __restrict__ Pl)
{
    long long base = (long long)blockIdx.x * 1024;
    int tid = threadIdx.x;
    __shared__ float red[256];
    float4 vv = *(const float4*)&Pin[base + tid * 4];
    float v[4] = {vv.x, vv.y, vv.z, vv.w};
    float mx = fmaxf(fmaxf(v[0], v[1]), fmaxf(v[2], v[3]));
    red[tid] = mx; __syncthreads();
    for (int s = 128; s > 0; s >>= 1) { if (tid < s) red[tid] = fmaxf(red[tid], red[tid + s]); __syncthreads(); }
    mx = red[0]; __syncthreads();
    float sum = 0.f;
    #pragma unroll
    for (int i = 0; i < 4; i++) { v[i] = __expf(v[i] - mx); sum += v[i]; }
    red[tid] = sum; __syncthreads();
    for (int s = 128; s > 0; s >>= 1) { if (tid < s) red[tid] += red[tid + s]; __syncthreads(); }
    float inv = 1.f / red[0];
    #pragma unroll
    for (int i = 0; i < 4; i++) v[i] *= inv;
    if (Pout) {
        vv.x = v[0]; vv.y = v[1]; vv.z = v[2]; vv.w = v[3];
        *(float4*)&Pout[base + tid * 4] = vv;
    }
    if (Ph) {
        __half2 h01, l01, h23, l23;
        split2(v[0], v[1], h01, l01);
        split2(v[2], v[3], h23, l23);
        *(__half2*)&Ph[base + tid * 4] = h01; *(__half2*)&Ph[base + tid * 4 + 2] = h23;
        *(__half2*)&Pl[base + tid * 4] = l01; *(__half2*)&Pl[base + tid * 4 + 2] = l23;
    }
}

// ---------------- layernorm ----------------
__global__ void ln_kernel(const float* __restrict__ a, const float* __restrict__ b,
                          const float* __restrict__ g, const float* __restrict__ beta,
                          float* __restrict__ out, float* __restrict__ out2,
                          __half* __restrict__ oh, __half* __restrict__ ol)
{
    long long base = (long long)blockIdx.x * 512;
    int tid = threadIdx.x;   // 128
    __shared__ float red[128];
    float4 xv = *(const float4*)&a[base + tid * 4];
    if (b) {
        float4 bv = *(const float4*)&b[base + tid * 4];
        xv.x += bv.x; xv.y += bv.y; xv.z += bv.z; xv.w += bv.w;
    }
    red[tid] = xv.x + xv.y + xv.z + xv.w; __syncthreads();
    for (int s = 64; s > 0; s >>= 1) { if (tid < s) red[tid] += red[tid + s]; __syncthreads(); }
    float mean = red[0] * (1.f / 512.f);
    __syncthreads();
    float d0 = xv.x - mean, d1 = xv.y - mean, d2 = xv.z - mean, d3 = xv.w - mean;
    red[tid] = d0 * d0 + d1 * d1 + d2 * d2 + d3 * d3; __syncthreads();
    for (int s = 64; s > 0; s >>= 1) { if (tid < s) red[tid] += red[tid + s]; __syncthreads(); }
    float rstd = rsqrtf(red[0] * (1.f / 512.f) + 1e-5f);
    float4 gv = *(const float4*)&g[tid * 4];
    float4 bt = *(const float4*)&beta[tid * 4];
    float4 ov;
    ov.x = d0 * rstd * gv.x + bt.x;
    ov.y = d1 * rstd * gv.y + bt.y;
    ov.z = d2 * rstd * gv.z + bt.z;
    ov.w = d3 * rstd * gv.w + bt.w;
    if (out)  *(float4*)&out[base + tid * 4]  = ov;
    if (out2) *(float4*)&out2[base + tid * 4] = ov;
    if (oh) {
        __half2 h01, l01, h23, l23;
        split2(ov.x, ov.y, h01, l01);
        split2(ov.z, ov.w, h23, l23);
        *(__half2*)&oh[base + tid * 4] = h01; *(__half2*)&oh[base + tid * 4 + 2] = h23;
        *(__half2*)&ol[base + tid * 4] = l01; *(__half2*)&ol[base + tid * 4 + 2] = l23;
    }
}

// ---------------- temporal "transpose-reshape" + split ----------------
__global__ void permute_split_kernel(const float* __restrict__ in,
                                     __half* __restrict__ oh, __half* __restrict__ ol)
{
    long long i = ((long long)blockIdx.x * 256 + threadIdx.x) * 2;
    if (i >= (long long)BLD) return;
    long long b = i / (LL * DDIM);
    int f = (int)(i - b * (LL * DDIM));
    const float* src = in + b * (LL * DDIM);
    float v0 = src[(long long)(f & (LL - 1)) * DDIM + (f >> 10)];
    float v1 = src[(long long)((f + 1) & (LL - 1)) * DDIM + ((f + 1) >> 10)];
    __half2 h, l; split2(v0, v1, h, l);
    *(__half2*)&oh[i] = h;
    *(__half2*)&ol[i] = l;
}

// ---------------- host dispatch ----------------
static void tcg(const __half* Ah, const __half* Al, const __half* Bh, const __half* Bl,
                float* C, __half* Ch, __half* Cl,
                const float* bias, const float* res,
                int M, int N, int K, int lda, int ldb, int ldc,
                float alpha, bool relu, int batch, int inner,
                long long sAo, long long sAi, long long sBo, long long sBi,
                long long sCo, long long sCi)
{
    if (N % 128 == 0) {
        dim3 g(N / 128, M / 128, batch);
        size_t sm = 3ull * (128 + 128) * 128;
        if (relu) {
            cudaFuncSetAttribute(hgemm<128, true , false>, cudaFuncAttributeMaxDynamicSharedMemorySize, (int)sm);
            hgemm<128, true , false><<<g, 256, sm>>>(Ah, Al, nullptr, Bh, Bl, C, Ch, Cl, bias, res, K, lda, ldb, ldc, alpha, inner, sAo, sAi, sBo, sBi, sCo, sCi);
        } else {
            cudaFuncSetAttribute(hgemm<128, false, false>, cudaFuncAttributeMaxDynamicSharedMemorySize, (int)sm);
            hgemm<128, false, false><<<g, 256, sm>>>(Ah, Al, nullptr, Bh, Bl, C, Ch, Cl, bias, res, K, lda, ldb, ldc, alpha, inner, sAo, sAi, sBo, sBi, sCo, sCi);
        }
    } else {
        dim3 g(N / 64, M / 128, batch);
        size_t sm = 3ull * (128 + 64) * 128;
        cudaFuncSetAttribute(hgemm<64, false, false>, cudaFuncAttributeMaxDynamicSharedMemorySize, (int)sm);
        hgemm<64, false, false><<<g, 256, sm>>>(Ah, Al, nullptr, Bh, Bl, C, Ch, Cl, bias, res, K, lda, ldb, ldc, alpha, inner, sAo, sAi, sBo, sBi, sCo, sCi);
    }
}

// fp32-A variant (outer A@V only, N=64)
static void tcg_splitA(const float* Af, const __half* Bh, const __half* Bl,
                       __half* Ch, __half* Cl,
                       int M, int N, int K, int lda, int ldb, int ldc,
                       int batch, int inner,
                       long long sAo, long long sAi, long long sBo, long long sBi,
                       long long sCo, long long sCi)
{
    dim3 g(N / 64, M / 128, batch);
    size_t sm = 3ull * (128 + 64) * 128;
    cudaFuncSetAttribute(hgemm<64, false, true>, cudaFuncAttributeMaxDynamicSharedMemorySize, (int)sm);
    hgemm<64, false, true><<<g, 256, sm>>>(nullptr, nullptr, Af, Bh, Bl, nullptr, Ch, Cl,
                                           nullptr, nullptr, K, lda, ldb, ldc, 1.f, inner,
                                           sAo, sAi, sBo, sBi, sCo, sCi);
}

extern "C" void kernel_launch(void* const* d_in, const int* in_sizes, int n_in,
                              void* d_out, int out_size)
{
    const float* x0   = (const float*)d_in[0];
    const float* aw_q = (const float*)d_in[1];   const float* ab_q = (const float*)d_in[2];
    const float* aw_k = (const float*)d_in[3];   const float* ab_k = (const float*)d_in[4];
    const float* aw_v = (const float*)d_in[5];   const float* ab_v = (const float*)d_in[6];
    const float* aw_o = (const float*)d_in[7];   const float* ab_o = (const float*)d_in[8];
    const float* n1g  = (const float*)d_in[9];   const float* n1b  = (const float*)d_in[10];
    const float* n2g  = (const float*)d_in[11];  const float* n2b  = (const float*)d_in[12];
    const float* tqw  = (const float*)d_in[13];  const float* tqb  = (const float*)d_in[14];
    const float* tkw  = (const float*)d_in[15];  const float* tkb  = (const float*)d_in[16];
    const float* tvw  = (const float*)d_in[17];  const float* tvb  = (const float*)d_in[18];
    const float* tow  = (const float*)d_in[19];  const float* tob  = (const float*)d_in[20];
    const float* tf1w = (const float*)d_in[21];  const float* tf1b = (const float*)d_in[22];
    const float* tf2w = (const float*)d_in[23];  const float* tf2b = (const float*)d_in[24];
    const float* tng  = (const float*)d_in[25];  const float* tnb  = (const float*)d_in[26];

    float *t, *t2, *x, *y, *s, *Afb, *qkvb, *tqkvb;
    cudaGetSymbolAddress((void**)&t,    g_t);
    cudaGetSymbolAddress((void**)&t2,   g_t2);
    cudaGetSymbolAddress((void**)&x,    g_x);
    cudaGetSymbolAddress((void**)&y,    g_y);
    cudaGetSymbolAddress((void**)&s,    g_s);
    cudaGetSymbolAddress((void**)&Afb,  g_A);
    cudaGetSymbolAddress((void**)&qkvb, g_qkvb);
    cudaGetSymbolAddress((void**)&tqkvb,g_tqkvb);

    __half *x0h,*x0l,*qkvh,*qkvl,*vth,*vtl,*th,*tl,*t2h,*t2l,*yh,*yl,*xnh,*xnl,*hh,*hl,*sh,*sl;
    __half *awqkvh,*awqkvl,*awoh,*awol,*tqkvwh,*tqkvwl,*towh,*towl,*f1h,*f1l,*f2h,*f2l;
    cudaGetSymbolAddress((void**)&x0h, g_x0h);   cudaGetSymbolAddress((void**)&x0l, g_x0l);
    cudaGetSymbolAddress((void**)&qkvh,g_qkvh);  cudaGetSymbolAddress((void**)&qkvl,g_qkvl);
    cudaGetSymbolAddress((void**)&vth, g_vth);   cudaGetSymbolAddress((void**)&vtl, g_vtl);
    cudaGetSymbolAddress((void**)&th,  g_th);    cudaGetSymbolAddress((void**)&tl,  g_tl);
    cudaGetSymbolAddress((void**)&t2h, g_t2h);   cudaGetSymbolAddress((void**)&t2l, g_t2l);
    cudaGetSymbolAddress((void**)&yh,  g_yh);    cudaGetSymbolAddress((void**)&yl,  g_yl);
    cudaGetSymbolAddress((void**)&xnh, g_xnh);   cudaGetSymbolAddress((void**)&xnl, g_xnl);
    cudaGetSymbolAddress((void**)&hh,  g_hh);    cudaGetSymbolAddress((void**)&hl,  g_hl);
    cudaGetSymbolAddress((void**)&sh,  g_sh);    cudaGetSymbolAddress((void**)&sl,  g_sl);
    cudaGetSymbolAddress((void**)&awqkvh, g_awqkvh); cudaGetSymbolAddress((void**)&awqkvl, g_awqkvl);
    cudaGetSymbolAddress((void**)&awoh, g_awoh); cudaGetSymbolAddress((void**)&awol, g_awol);
    cudaGetSymbolAddress((void**)&tqkvwh, g_tqkvwh); cudaGetSymbolAddress((void**)&tqkvwl, g_tqkvwl);
    cudaGetSymbolAddress((void**)&towh, g_towh); cudaGetSymbolAddress((void**)&towl, g_towl);
    cudaGetSymbolAddress((void**)&f1h, g_f1h);   cudaGetSymbolAddress((void**)&f1l, g_f1l);
    cudaGetSymbolAddress((void**)&f2h, g_f2h);   cudaGetSymbolAddress((void**)&f2l, g_f2l);

    float* out_ln = (float*)d_out;
    float* Ap = (out_size >= (BLD + BHLL)) ? ((float*)d_out + BLD) : Afb;

    const int M = BB * LL;
    const long long LD  = (long long)LL * DDIM;
    const long long LLs = (long long)LL * LL;
    const long long QROW = (long long)LL * NQKV;
    dim3 tb(32, 8);

    bias_pack_kernel<<<(NQKV + 255) / 256, 256>>>(ab_q, ab_k, ab_v, tqb, tkb, tvb, qkvb, tqkvb);

    transpose_split_kernel<<<dim3(16,16,1), tb>>>(aw_q, awqkvh + 0*DD2, awqkvl + 0*DD2, DDIM, DDIM, DD2, DD2);
    transpose_split_kernel<<<dim3(16,16,1), tb>>>(aw_k, awqkvh + 1*DD2, awqkvl + 1*DD2, DDIM, DDIM, DD2, DD2);
    transpose_split_kernel<<<dim3(16,16,1), tb>>>(aw_v, awqkvh + 2*DD2, awqkvl + 2*DD2, DDIM, DDIM, DD2, DD2);
    transpose_split_kernel<<<dim3(16,16,1), tb>>>(aw_o, awoh, awol, DDIM, DDIM, DD2, DD2);
    split_kernel<<<(BLD/4 + 255)/256, 256>>>(x0, x0h, x0l, BLD/4);

    // ---- outer MHA: fused QKV (N=1536) ----
    tcg(x0h, x0l, awqkvh, awqkvl, nullptr, qkvh, qkvl, qkvb, nullptr,
        M, NQKV, DDIM, DDIM, DDIM, NQKV, 1.f, false, 1, 1, 0,0,0,0,0,0);
    transpose_halves_kernel<<<dim3(16,32,BB), tb>>>(qkvh + 1024, qkvl + 1024, NQKV, QROW,
                                                    vth, vtl, LL, LD);
    // scores -> Ap fp32
    tcg(qkvh + 0, qkvl + 0, qkvh + 512, qkvl + 512, Ap, nullptr, nullptr, nullptr, nullptr,
        LL, LL, EE, NQKV, NQKV, LL, 0.125f, false,
        BB * HH, HH, QROW, EE, QROW, EE, (long long)HH * LLs, LLs);
    // softmax: fp32 probs only (A output); no halves
    softmax_kernel<<<BB * HH * LL, 256>>>(Ap, Ap, nullptr, nullptr);
    // A@V: A = fp32 probs, split in-kernel -> t halves
    tcg_splitA(Ap, vth, vtl, th, tl,
               LL, EE, LL, LL, LL, DDIM,
               BB * HH, HH, (long long)HH * LLs, LLs, LD, (long long)EE * LL, LD, EE);
    // t2 = t @ aw_o + ab_o + x0 ; x = LN(t2)
    tcg(th, tl, awoh, awol, t2, nullptr, nullptr, ab_o, x0,
        M, DDIM, DDIM, DDIM, DDIM, DDIM, 1.f, false, 1, 1, 0,0,0,0,0,0);
    ln_kernel<<<M, 128>>>(t2, nullptr, n1g, n1b, x, y, yh, yl);

    // ---- temporal weight preps ----
    transpose_split_kernel<<<dim3(16,16,NBLK), tb>>>(tqw, tqkvwh + 0*DD2, tqkvwl + 0*DD2, DDIM, DDIM, DD2, 3LL*DD2);
    transpose_split_kernel<<<dim3(16,16,NBLK), tb>>>(tkw, tqkvwh + 1*DD2, tqkvwl + 1*DD2, DDIM, DDIM, DD2, 3LL*DD2);
    transpose_split_kernel<<<dim3(16,16,NBLK), tb>>>(tvw, tqkvwh + 2*DD2, tqkvwl + 2*DD2, DDIM, DDIM, DD2, 3LL*DD2);
    transpose_split_kernel<<<dim3(16,16,NBLK), tb>>>(tow, towh, towl, DDIM, DDIM, DD2, DD2);
    transpose_split_kernel<<<dim3(64,16,NBLK), tb>>>(tf1w, f1h, f1l, DDIM, DFF, (long long)DDIM*DFF, (long long)DDIM*DFF);
    transpose_split_kernel<<<dim3(16,64,NBLK), tb>>>(tf2w, f2h, f2l, DFF, DDIM, (long long)DFF*DDIM, (long long)DFF*DDIM);

    // ---- temporal blocks ----
    for (int i = 0; i < NBLK; i++) {
        const __half* Wqkvh = tqkvwh + (long long)i * 3 * DD2;
        const __half* Wqkvl = tqkvwl + (long long)i * 3 * DD2;
        const __half* Woh = towh + (long long)i * DD2;  const __half* Wol = towl + (long long)i * DD2;
        const __half* W1h = f1h + (long long)i * DDIM * DFF;  const __half* W1l = f1l + (long long)i * DDIM * DFF;
        const __half* W2h = f2h + (long long)i * DFF * DDIM;  const __half* W2l = f2l + (long long)i * DFF * DDIM;
        const float* bqkv = tqkvb + i * NQKV;
        const float* bo = tob + i * DDIM;
        const float* b1 = tf1b + i * DFF;  const float* b2 = tf2b + i * DDIM;
        const float* ng = tng + i * DDIM;  const float* nb = tnb + i * DDIM;

        tcg(yh, yl, Wqkvh, Wqkvl, nullptr, qkvh, qkvl, bqkv, nullptr,
            M, NQKV, DDIM, DDIM, DDIM, NQKV, 1.f, false, 1, 1, 0,0,0,0,0,0);
        transpose_halves_kernel<<<dim3(16,32,BB), tb>>>(qkvh + 1024, qkvl + 1024, NQKV, QROW,
                                                        vth, vtl, LL, LD);
        tcg(qkvh + 0, qkvl + 0, qkvh + 512, qkvl + 512, s, nullptr, nullptr, nullptr, nullptr,
            LL, LL, DDIM, NQKV, NQKV, LL, 1.f, false,
            BB, 1, QROW, 0, QROW, 0, LLs, 0);
        softmax_kernel<<<BB * LL, 256>>>(s, nullptr, sh, sl);
        tcg(sh, sl, vth, vtl, t, nullptr, nullptr, nullptr, nullptr,
            LL, DDIM, LL, LL, LL, DDIM, 1.f, false,
            BB, 1, LLs, 0, LD, 0, LD, 0);
        permute_split_kernel<<<(BLD/2 + 255)/256, 256>>>(t, t2h, t2l);
        tcg(t2h, t2l, Woh, Wol, y, yh, yl, bo, y,
            M, DDIM, DDIM, DDIM, DDIM, DDIM, 1.f, false, 1, 1, 0,0,0,0,0,0);

        ln_kernel<<<M, 128>>>(y, nullptr, ng, nb, nullptr, nullptr, xnh, xnl);
        tcg(xnh, xnl, W1h, W1l, nullptr, hh, hl, b1, nullptr,
            M, DFF, DDIM, DDIM, DDIM, DFF, 1.f, true, 1, 1, 0,0,0,0,0,0);
        tcg(hh, hl, W2h, W2l, y, yh, yl, b2, y,
            M, DDIM, DFF, DFF, DFF, DDIM, 1.f, false, 1, 1, 0,0,0,0,0,0);
    }

    ln_kernel<<<M, 128>>>(x, y, n2g, n2b, out_ln, nullptr, nullptr, nullptr);
}

// round 15
// speedup vs baseline: 1.5544x; 1.5544x over previous
#include <cuda_runtime.h>
#include <cuda_fp16.h>
#include <cstdint>

#define BB   8
#define LL   1024
#define DDIM 512
#define HH   8
#define EE   64
#define DFF  2048
#define NBLK 3
#define NQKV 1536
#define BLD  (BB*LL*DDIM)
#define BLQ  (BB*LL*NQKV)
#define BLL  (BB*LL*LL)
#define BHLL (BB*HH*LL*LL)
#define BLDF (BB*LL*DFF)
#define DD2  (DDIM*DDIM)

// ---------------- fp32 scratch ----------------
__device__ float g_t[BLD];
__device__ float g_t2[BLD];
__device__ float g_x[BLD];
__device__ float g_y[BLD];
__device__ float g_s[BLL];
__device__ float g_A[BHLL];
__device__ float g_qkvb[NQKV];
__device__ float g_tqkvb[NBLK*NQKV];
// ---------------- half hi/lo scratch ----------------
__device__ __half g_x0h[BLD],  g_x0l[BLD];
__device__ __half g_qkvh[BLQ], g_qkvl[BLQ];
__device__ __half g_vth[BLD],  g_vtl[BLD];
__device__ __half g_th[BLD],   g_tl[BLD];
__device__ __half g_t2h[BLD],  g_t2l[BLD];
__device__ __half g_yh[BLD],   g_yl[BLD];
__device__ __half g_xnh[BLD],  g_xnl[BLD];
__device__ __half g_hh[BLDF],  g_hl[BLDF];
__device__ __half g_sh[BHLL],  g_sl[BHLL];
__device__ __half g_awqkvh[3*DD2], g_awqkvl[3*DD2];
__device__ __half g_awoh[DD2],     g_awol[DD2];
__device__ __half g_tqkvwh[NBLK*3*DD2], g_tqkvwl[NBLK*3*DD2];
__device__ __half g_towh[NBLK*DD2],     g_towl[NBLK*DD2];
__device__ __half g_f1h[NBLK*DDIM*DFF], g_f1l[NBLK*DDIM*DFF];
__device__ __half g_f2h[NBLK*DFF*DDIM], g_f2l[NBLK*DFF*DDIM];

// ---------------- helpers ----------------
#define SWZ(o) ((uint32_t)(o) ^ ((((uint32_t)(o)) >> 3) & 0x70u))

__device__ __forceinline__ void mma16816(float* d, const uint32_t* a, uint32_t b0, uint32_t b1) {
    asm volatile(
        "mma.sync.aligned.m16n8k16.row.col.f32.f16.f16.f32 "
        "{%0,%1,%2,%3}, {%4,%5,%6,%7}, {%8,%9}, {%0,%1,%2,%3};"
        : "+f"(d[0]), "+f"(d[1]), "+f"(d[2]), "+f"(d[3])
        : "r"(a[0]), "r"(a[1]), "r"(a[2]), "r"(a[3]), "r"(b0), "r"(b1));
}
__device__ __forceinline__ void ldm_x4(uint32_t* r, uint32_t addr) {
    asm volatile("ldmatrix.sync.aligned.m8n8.x4.shared.b16 {%0,%1,%2,%3}, [%4];"
        : "=r"(r[0]), "=r"(r[1]), "=r"(r[2]), "=r"(r[3]) : "r"(addr));
}
__device__ __forceinline__ void cp16(uint32_t dst, const void* src) {
    asm volatile("cp.async.cg.shared.global [%0], [%1], 16;" :: "r"(dst), "l"(src));
}
#define CP_COMMIT() asm volatile("cp.async.commit_group;" ::: "memory")
#define CP_WAIT1()  asm volatile("cp.async.wait_group 1;" ::: "memory")

__device__ __forceinline__ void split2(float x, float y, __half2& h, __half2& l) {
    h = __floats2half2_rn(x, y);
    float2 f = __half22float2(h);
    l = __floats2half2_rn(x - f.x, y - f.y);
}

// ============ fp16 hi/lo split tensor GEMM (3-term, fp32-grade) ============
// C = alpha*A@B^T (+bias)(+res)(relu). A,B hi/lo half arrays, K-major.
// CTA 128xBN, 256 threads = 8 warps, warp tile 32x(BN/2). 3-stage pipeline, 2 CTAs/SM.
template<int BN, bool RELU>
__global__ void __launch_bounds__(256, 2) hgemm(
    const __half* __restrict__ Ah, const __half* __restrict__ Al,
    const __half* __restrict__ Bh, const __half* __restrict__ Bl,
    float* __restrict__ C, __half* __restrict__ Ch, __half* __restrict__ Cl,
    const float* __restrict__ bias, const float* __restrict__ res,
    int K, int lda, int ldb, int ldc, float alpha, int inner,
    long long sAo, long long sAi, long long sBo, long long sBi,
    long long sCo, long long sCi)
{
    constexpr int NA   = BN / 16;
    constexpr int ABYT = 128 * 128;
    constexpr int BBYT = BN * 128;
    constexpr int STG  = ABYT + BBYT;
    constexpr int AIT  = 4;
    constexpr int BIT  = BN * 8 / 256;

    extern __shared__ char smch[];
    const uint32_t smb0 = (uint32_t)__cvta_generic_to_shared(smch);

    int z  = blockIdx.z;
    int zo = z / inner;
    int zi = z - zo * inner;
    Ah += zo * sAo + zi * sAi;  Al += zo * sAo + zi * sAi;
    Bh += zo * sBo + zi * sBi;  Bl += zo * sBo + zi * sBi;
    long long coff = zo * sCo + zi * sCi;
    if (C)  C  += coff;
    if (Ch) { Ch += coff; Cl += coff; }
    if (res) res += coff;

    const int tid  = threadIdx.x;
    const int wid  = tid >> 5, lane = tid & 31;
    const int g    = lane >> 2, t4 = lane & 3;
    const int row0 = blockIdx.y * 128, col0 = blockIdx.x * BN;
    const int arow = (wid & 3) * 32;
    const int brow = (wid >> 2) * (BN / 2);

    const int a_r   = arow + (lane & 15);
    const int a_q   = lane >> 4;
    const int b_mat = lane >> 3, b_row = lane & 7;
    const int b_n   = brow + (b_mat >> 1) * 8 + b_row;
    const int b_q   = b_mat & 1;

    float acc[2][NA][4];
    #pragma unroll
    for (int i = 0; i < 2; i++)
        #pragma unroll
        for (int j = 0; j < NA; j++)
            #pragma unroll
            for (int e = 0; e < 4; e++) acc[i][j][e] = 0.f;

    const int NC = K >> 5;

    auto issue_stage = [&](int c, int st) {
        if (c < NC) {
            const int k0 = c << 5;
            uint32_t sA = smb0 + st * STG;
            uint32_t sB = sA + ABYT;
            #pragma unroll
            for (int i = 0; i < AIT; i++) {
                int cb = tid + i * 256;
                int r = cb >> 3, sub = cb & 7;
                const __half* src = (sub < 4 ? Ah : Al) + (size_t)(row0 + r) * lda + k0 + (sub & 3) * 8;
                cp16(sA + SWZ(r * 128 + sub * 16), src);
            }
            #pragma unroll
            for (int i = 0; i < BIT; i++) {
                int cb = tid + i * 256;
                int r = cb >> 3, sub = cb & 7;
                const __half* src = (sub < 4 ? Bh : Bl) + (size_t)(col0 + r) * ldb + k0 + (sub & 3) * 8;
                cp16(sB + SWZ(r * 128 + sub * 16), src);
            }
        }
        CP_COMMIT();
    };

    issue_stage(0, 0);
    issue_stage(1, 1);

    for (int c = 0; c < NC; c++) {
        CP_WAIT1();
        __syncthreads();
        issue_stage(c + 2, (c + 2) % 3);

        const uint32_t sA = smb0 + (c % 3) * STG;
        const uint32_t sB = sA + ABYT;

        #pragma unroll
        for (int ka = 0; ka < 2; ka++) {
            uint32_t ah[2][4], al[2][4];
            #pragma unroll
            for (int ma = 0; ma < 2; ma++) {
                uint32_t off = (uint32_t)(a_r + ma * 16) * 128u + (uint32_t)(ka * 2 + a_q) * 16u;
                ldm_x4(ah[ma], sA + SWZ(off));
                ldm_x4(al[ma], sA + SWZ(off + 64));
            }
            #pragma unroll
            for (int p = 0; p < NA / 2; p++) {
                uint32_t off = (uint32_t)(b_n + p * 16) * 128u + (uint32_t)(ka * 2 + b_q) * 16u;
                uint32_t bh[4], bl[4];
                ldm_x4(bh, sB + SWZ(off));
                ldm_x4(bl, sB + SWZ(off + 64));
                #pragma unroll
                for (int e = 0; e < 2; e++) {
                    #pragma unroll
                    for (int ma = 0; ma < 2; ma++) {
                        float* ac = acc[ma][p * 2 + e];
                        mma16816(ac, ah[ma], bh[e * 2], bh[e * 2 + 1]);
                        mma16816(ac, ah[ma], bl[e * 2], bl[e * 2 + 1]);
                        mma16816(ac, al[ma], bh[e * 2], bh[e * 2 + 1]);
                    }
                }
            }
        }
    }

    // ---- epilogue ----
    #pragma unroll
    for (int ma = 0; ma < 2; ma++) {
        #pragma unroll
        for (int na = 0; na < NA; na++) {
            int r_ = row0 + arow + ma * 16 + g;
            int n_ = col0 + brow + na * 8 + t4 * 2;
            float2 bb = bias ? *(const float2*)&bias[n_] : make_float2(0.f, 0.f);
            #pragma unroll
            for (int hf = 0; hf < 2; hf++) {
                int m = r_ + hf * 8;
                float2 v;
                v.x = acc[ma][na][hf * 2 + 0] * alpha + bb.x;
                v.y = acc[ma][na][hf * 2 + 1] * alpha + bb.y;
                if (res) {
                    float2 rr = *(const float2*)&res[(size_t)m * ldc + n_];
                    v.x += rr.x; v.y += rr.y;
                }
                if (RELU) { v.x = fmaxf(v.x, 0.f); v.y = fmaxf(v.y, 0.f); }
                if (C) *(float2*)&C[(size_t)m * ldc + n_] = v;
                if (Ch) {
                    __half2 h2, l2; split2(v.x, v.y, h2, l2);
                    *(__half2*)&Ch[(size_t)m * ldc + n_] = h2;
                    *(__half2*)&Cl[(size_t)m * ldc + n_] = l2;
                }
            }
        }
    }
}

// ---------------- transpose(+split): out[C,R] halves = split(in[R,C]^T) ----------------
__global__ void transpose_split_kernel(const float* __restrict__ in,
                                       __half* __restrict__ oh, __half* __restrict__ ol,
                                       int R, int C, long long in_bs, long long out_bs)
{
    __shared__ float tile[32][33];
    long long bi = (long long)blockIdx.z * in_bs;
    long long bo = (long long)blockIdx.z * out_bs;
    int c0 = blockIdx.x * 32, r0 = blockIdx.y * 32;
    int tx = threadIdx.x, ty = threadIdx.y;
    #pragma unroll
    for (int j = 0; j < 4; j++)
        tile[ty + j * 8][tx] = in[bi + (long long)(r0 + ty + j * 8) * C + c0 + tx];
    __syncthreads();
    #pragma unroll
    for (int j = 0; j < 4; j++) {
        float v = tile[tx][ty + j * 8];
        __half h = __float2half_rn(v);
        __half l = __float2half_rn(v - __half2float(h));
        long long idx = bo + (long long)(c0 + ty + j * 8) * R + r0 + tx;
        oh[idx] = h; ol[idx] = l;
    }
}

// ---------------- transpose passthrough of pre-split halves ----------------
__global__ void transpose_halves_kernel(const __half* __restrict__ inh, const __half* __restrict__ inl,
                                        int ldin, long long in_bs,
                                        __half* __restrict__ outh, __half* __restrict__ outl,
                                        int ldout, long long out_bs)
{
    __shared__ uint32_t tile[32][33];
    long long bi = (long long)blockIdx.z * in_bs;
    long long bo = (long long)blockIdx.z * out_bs;
    int c0 = blockIdx.x * 32, r0 = blockIdx.y * 32;
    int tx = threadIdx.x, ty = threadIdx.y;
    #pragma unroll
    for (int j = 0; j < 4; j++) {
        long long idx = bi + (long long)(r0 + ty + j * 8) * ldin + c0 + tx;
        uint32_t h = __half_as_ushort(inh[idx]);
        uint32_t l = __half_as_ushort(inl[idx]);
        tile[ty + j * 8][tx] = h | (l << 16);
    }
    __syncthreads();
    #pragma unroll
    for (int j = 0; j < 4; j++) {
        uint32_t u = tile[tx][ty + j * 8];
        long long idx = bo + (long long)(c0 + ty + j * 8) * ldout + r0 + tx;
        outh[idx] = __ushort_as_half((unsigned short)(u & 0xFFFFu));
        outl[idx] = __ushort_as_half((unsigned short)(u >> 16));
    }
}

// ---------------- elementwise split ----------------
__global__ void split_kernel(const float* __restrict__ in,
                             __half* __restrict__ oh, __half* __restrict__ ol, int n4)
{
    int i = blockIdx.x * 256 + threadIdx.x;
    if (i >= n4) return;
    float4 v = ((const float4*)in)[i];
    __half2 h01, l01, h23, l23;
    split2(v.x, v.y, h01, l01);
    split2(v.z, v.w, h23, l23);
    ((__half2*)oh)[i * 2] = h01; ((__half2*)oh)[i * 2 + 1] = h23;
    ((__half2*)ol)[i * 2] = l01; ((__half2*)ol)[i * 2 + 1] = l23;
}

// ---------------- bias packing: one kernel replaces 12 graph memcpy nodes ----------------
__global__ void bias_pack_kernel(const float* __restrict__ ab_q, const float* __restrict__ ab_k,
                                 const float* __restrict__ ab_v,
                                 const float* __restrict__ tqb, const float* __restrict__ tkb,
                                 const float* __restrict__ tvb,
                                 float* __restrict__ qkvb, float* __restrict__ tqkvb)
{
    int i = blockIdx.x * 256 + threadIdx.x;   // 0..1535
    if (i < NQKV) {
        int sec = i >> 9, off = i & 511;
        qkvb[i] = (sec == 0 ? ab_q : sec == 1 ? ab_k : ab_v)[off];
        for (int b = 0; b < NBLK; b++) {
            const float* src = (sec == 0 ? tqb : sec == 1 ? tkb : tvb) + b * DDIM;
            tqkvb[b * NQKV + i] = src[off];
        }
    }
}

// ---------------- softmax rows of 1024; optional fp32 writeback + halves out ----------------
__global__ void softmax_kernel(const float* __restrict__ Pin, float* __restrict__ Pout,
                               __half* __restrict__ Ph, __half* __restrict__ Pl)
{
    long long base = (long long)blockIdx.x * 1024;
    int tid = threadIdx.x;
    __shared__ float red[256];
    float4 vv = *(const float4*)&Pin[base + tid * 4];
    float v[4] = {vv.x, vv.y, vv.z, vv.w};
    float mx = fmaxf(fmaxf(v[0], v[1]), fmaxf(v[2], v[3]));
    red[tid] = mx; __syncthreads();
    for (int s = 128; s > 0; s >>= 1) { if (tid < s) red[tid] = fmaxf(red[tid], red[tid + s]); __syncthreads(); }
    mx = red[0]; __syncthreads();
    float sum = 0.f;
    #pragma unroll
    for (int i = 0; i < 4; i++) { v[i] = __expf(v[i] - mx); sum += v[i]; }
    red[tid] = sum; __syncthreads();
    for (int s = 128; s > 0; s >>= 1) { if (tid < s) red[tid] += red[tid + s]; __syncthreads(); }
    float inv = 1.f / red[0];
    #pragma unroll
    for (int i = 0; i < 4; i++) v[i] *= inv;
    if (Pout) {
        vv.x = v[0]; vv.y = v[1]; vv.z = v[2]; vv.w = v[3];
        *(float4*)&Pout[base + tid * 4] = vv;
    }
    __half2 h01, l01, h23, l23;
    split2(v[0], v[1], h01, l01);
    split2(v[2], v[3], h23, l23);
    *(__half2*)&Ph[base + tid * 4] = h01; *(__half2*)&Ph[base + tid * 4 + 2] = h23;
    *(__half2*)&Pl[base + tid * 4] = l01; *(__half2*)&Pl[base + tid * 4 + 2] = l23;
}

// ---------------- layernorm; optional 2x fp32 out + optional halves out ----------------
__global__ void ln_kernel(const float* __restrict__ a, const float* __restrict__ b,
                          const float* __restrict__ g, const float* __restrict__ beta,
                          float* __restrict__ out, float* __restrict__ out2,
                          __half* __restrict__ oh, __half* __restrict__ ol)
{
    long long base = (long long)blockIdx.x * 512;
    int tid = threadIdx.x;   // 128
    __shared__ float red[128];
    float4 xv = *(const float4*)&a[base + tid * 4];
    if (b) {
        float4 bv = *(const float4*)&b[base + tid * 4];
        xv.x += bv.x; xv.y += bv.y; xv.z += bv.z; xv.w += bv.w;
    }
    red[tid] = xv.x + xv.y + xv.z + xv.w; __syncthreads();
    for (int s = 64; s > 0; s >>= 1) { if (tid < s) red[tid] += red[tid + s]; __syncthreads(); }
    float mean = red[0] * (1.f / 512.f);
    __syncthreads();
    float d0 = xv.x - mean, d1 = xv.y - mean, d2 = xv.z - mean, d3 = xv.w - mean;
    red[tid] = d0 * d0 + d1 * d1 + d2 * d2 + d3 * d3; __syncthreads();
    for (int s = 64; s > 0; s >>= 1) { if (tid < s) red[tid] += red[tid + s]; __syncthreads(); }
    float rstd = rsqrtf(red[0] * (1.f / 512.f) + 1e-5f);
    float4 gv = *(const float4*)&g[tid * 4];
    float4 bt = *(const float4*)&beta[tid * 4];
    float4 ov;
    ov.x = d0 * rstd * gv.x + bt.x;
    ov.y = d1 * rstd * gv.y + bt.y;
    ov.z = d2 * rstd * gv.z + bt.z;
    ov.w = d3 * rstd * gv.w + bt.w;
    if (out)  *(float4*)&out[base + tid * 4]  = ov;
    if (out2) *(float4*)&out2[base + tid * 4] = ov;
    if (oh) {
        __half2 h01, l01, h23, l23;
        split2(ov.x, ov.y, h01, l01);
        split2(ov.z, ov.w, h23, l23);
        *(__half2*)&oh[base + tid * 4] = h01; *(__half2*)&oh[base + tid * 4 + 2] = h23;
        *(__half2*)&ol[base + tid * 4] = l01; *(__half2*)&ol[base + tid * 4 + 2] = l23;
    }
}

// ---------------- temporal "transpose-reshape" + split (fp32 gather -> halves) ----------------
__global__ void permute_split_kernel(const float* __restrict__ in,
                                     __half* __restrict__ oh, __half* __restrict__ ol)
{
    long long i = ((long long)blockIdx.x * 256 + threadIdx.x) * 2;
    if (i >= (long long)BLD) return;
    long long b = i / (LL * DDIM);
    int f = (int)(i - b * (LL * DDIM));
    const float* src = in + b * (LL * DDIM);
    float v0 = src[(long long)(f & (LL - 1)) * DDIM + (f >> 10)];
    float v1 = src[(long long)((f + 1) & (LL - 1)) * DDIM + ((f + 1) >> 10)];
    __half2 h, l; split2(v0, v1, h, l);
    *(__half2*)&oh[i] = h;
    *(__half2*)&ol[i] = l;
}

// ---------------- host dispatch ----------------
static void tcg(const __half* Ah, const __half* Al, const __half* Bh, const __half* Bl,
                float* C, __half* Ch, __half* Cl,
                const float* bias, const float* res,
                int M, int N, int K, int lda, int ldb, int ldc,
                float alpha, bool relu, int batch, int inner,
                long long sAo, long long sAi, long long sBo, long long sBi,
                long long sCo, long long sCi)
{
    if (N % 128 == 0) {
        dim3 g(N / 128, M / 128, batch);
        size_t sm = 3ull * (128 + 128) * 128;   // 98304
        if (relu) {
            cudaFuncSetAttribute(hgemm<128, true >, cudaFuncAttributeMaxDynamicSharedMemorySize, (int)sm);
            hgemm<128, true ><<<g, 256, sm>>>(Ah, Al, Bh, Bl, C, Ch, Cl, bias, res, K, lda, ldb, ldc, alpha, inner, sAo, sAi, sBo, sBi, sCo, sCi);
        } else {
            cudaFuncSetAttribute(hgemm<128, false>, cudaFuncAttributeMaxDynamicSharedMemorySize, (int)sm);
            hgemm<128, false><<<g, 256, sm>>>(Ah, Al, Bh, Bl, C, Ch, Cl, bias, res, K, lda, ldb, ldc, alpha, inner, sAo, sAi, sBo, sBi, sCo, sCi);
        }
    } else { // N == 64
        dim3 g(N / 64, M / 128, batch);
        size_t sm = 3ull * (128 + 64) * 128;    // 73728
        cudaFuncSetAttribute(hgemm<64, false>, cudaFuncAttributeMaxDynamicSharedMemorySize, (int)sm);
        hgemm<64, false><<<g, 256, sm>>>(Ah, Al, Bh, Bl, C, Ch, Cl, bias, res, K, lda, ldb, ldc, alpha, inner, sAo, sAi, sBo, sBi, sCo, sCi);
    }
}

extern "C" void kernel_launch(void* const* d_in, const int* in_sizes, int n_in,
                              void* d_out, int out_size)
{
    const float* x0   = (const float*)d_in[0];
    const float* aw_q = (const float*)d_in[1];   const float* ab_q = (const float*)d_in[2];
    const float* aw_k = (const float*)d_in[3];   const float* ab_k = (const float*)d_in[4];
    const float* aw_v = (const float*)d_in[5];   const float* ab_v = (const float*)d_in[6];
    const float* aw_o = (const float*)d_in[7];   const float* ab_o = (const float*)d_in[8];
    const float* n1g  = (const float*)d_in[9];   const float* n1b  = (const float*)d_in[10];
    const float* n2g  = (const float*)d_in[11];  const float* n2b  = (const float*)d_in[12];
    const float* tqw  = (const float*)d_in[13];  const float* tqb  = (const float*)d_in[14];
    const float* tkw  = (const float*)d_in[15];  const float* tkb  = (const float*)d_in[16];
    const float* tvw  = (const float*)d_in[17];  const float* tvb  = (const float*)d_in[18];
    const float* tow  = (const float*)d_in[19];  const float* tob  = (const float*)d_in[20];
    const float* tf1w = (const float*)d_in[21];  const float* tf1b = (const float*)d_in[22];
    const float* tf2w = (const float*)d_in[23];  const float* tf2b = (const float*)d_in[24];
    const float* tng  = (const float*)d_in[25];  const float* tnb  = (const float*)d_in[26];

    float *t, *t2, *x, *y, *s, *Afb, *qkvb, *tqkvb;
    cudaGetSymbolAddress((void**)&t,    g_t);
    cudaGetSymbolAddress((void**)&t2,   g_t2);
    cudaGetSymbolAddress((void**)&x,    g_x);
    cudaGetSymbolAddress((void**)&y,    g_y);
    cudaGetSymbolAddress((void**)&s,    g_s);
    cudaGetSymbolAddress((void**)&Afb,  g_A);
    cudaGetSymbolAddress((void**)&qkvb, g_qkvb);
    cudaGetSymbolAddress((void**)&tqkvb,g_tqkvb);

    __half *x0h,*x0l,*qkvh,*qkvl,*vth,*vtl,*th,*tl,*t2h,*t2l,*yh,*yl,*xnh,*xnl,*hh,*hl,*sh,*sl;
    __half *awqkvh,*awqkvl,*awoh,*awol,*tqkvwh,*tqkvwl,*towh,*towl,*f1h,*f1l,*f2h,*f2l;
    cudaGetSymbolAddress((void**)&x0h, g_x0h);   cudaGetSymbolAddress((void**)&x0l, g_x0l);
    cudaGetSymbolAddress((void**)&qkvh,g_qkvh);  cudaGetSymbolAddress((void**)&qkvl,g_qkvl);
    cudaGetSymbolAddress((void**)&vth, g_vth);   cudaGetSymbolAddress((void**)&vtl, g_vtl);
    cudaGetSymbolAddress((void**)&th,  g_th);    cudaGetSymbolAddress((void**)&tl,  g_tl);
    cudaGetSymbolAddress((void**)&t2h, g_t2h);   cudaGetSymbolAddress((void**)&t2l, g_t2l);
    cudaGetSymbolAddress((void**)&yh,  g_yh);    cudaGetSymbolAddress((void**)&yl,  g_yl);
    cudaGetSymbolAddress((void**)&xnh, g_xnh);   cudaGetSymbolAddress((void**)&xnl, g_xnl);
    cudaGetSymbolAddress((void**)&hh,  g_hh);    cudaGetSymbolAddress((void**)&hl,  g_hl);
    cudaGetSymbolAddress((void**)&sh,  g_sh);    cudaGetSymbolAddress((void**)&sl,  g_sl);
    cudaGetSymbolAddress((void**)&awqkvh, g_awqkvh); cudaGetSymbolAddress((void**)&awqkvl, g_awqkvl);
    cudaGetSymbolAddress((void**)&awoh, g_awoh); cudaGetSymbolAddress((void**)&awol, g_awol);
    cudaGetSymbolAddress((void**)&tqkvwh, g_tqkvwh); cudaGetSymbolAddress((void**)&tqkvwl, g_tqkvwl);
    cudaGetSymbolAddress((void**)&towh, g_towh); cudaGetSymbolAddress((void**)&towl, g_towl);
    cudaGetSymbolAddress((void**)&f1h, g_f1h);   cudaGetSymbolAddress((void**)&f1l, g_f1l);
    cudaGetSymbolAddress((void**)&f2h, g_f2h);   cudaGetSymbolAddress((void**)&f2l, g_f2l);

    float* out_ln = (float*)d_out;
    float* Ap = (out_size >= (BLD + BHLL)) ? ((float*)d_out + BLD) : Afb;

    const int M = BB * LL;
    const long long LD  = (long long)LL * DDIM;
    const long long LLs = (long long)LL * LL;
    const long long QROW = (long long)LL * NQKV;
    dim3 tb(32, 8);

    // ---- combined biases (one kernel instead of 12 memcpy nodes) ----
    bias_pack_kernel<<<(NQKV + 255) / 256, 256>>>(ab_q, ab_k, ab_v, tqb, tkb, tvb, qkvb, tqkvb);

    // ---- preps for outer section ----
    transpose_split_kernel<<<dim3(16,16,1), tb>>>(aw_q, awqkvh + 0*DD2, awqkvl + 0*DD2, DDIM, DDIM, DD2, DD2);
    transpose_split_kernel<<<dim3(16,16,1), tb>>>(aw_k, awqkvh + 1*DD2, awqkvl + 1*DD2, DDIM, DDIM, DD2, DD2);
    transpose_split_kernel<<<dim3(16,16,1), tb>>>(aw_v, awqkvh + 2*DD2, awqkvl + 2*DD2, DDIM, DDIM, DD2, DD2);
    transpose_split_kernel<<<dim3(16,16,1), tb>>>(aw_o, awoh, awol, DDIM, DDIM, DD2, DD2);
    split_kernel<<<(BLD/4 + 255)/256, 256>>>(x0, x0h, x0l, BLD/4);

    // ---- outer MHA: fused QKV (N=1536) ----
    tcg(x0h, x0l, awqkvh, awqkvl, nullptr, qkvh, qkvl, qkvb, nullptr,
        M, NQKV, DDIM, DDIM, DDIM, NQKV, 1.f, false, 1, 1, 0,0,0,0,0,0);
    transpose_halves_kernel<<<dim3(16,32,BB), tb>>>(qkvh + 1024, qkvl + 1024, NQKV, QROW,
                                                    vth, vtl, LL, LD);
    // scores: q_h @ k_h^T / 8 -> Ap fp32
    tcg(qkvh + 0, qkvl + 0, qkvh + 512, qkvl + 512, Ap, nullptr, nullptr, nullptr, nullptr,
        LL, LL, EE, NQKV, NQKV, LL, 0.125f, false,
        BB * HH, HH, QROW, EE, QROW, EE, (long long)HH * LLs, LLs);
    softmax_kernel<<<BB * HH * LL, 256>>>(Ap, Ap, sh, sl);
    // out = A @ v_h -> t halves
    tcg(sh, sl, vth, vtl, nullptr, th, tl, nullptr, nullptr,
        LL, EE, LL, LL, LL, DDIM, 1.f, false,
        BB * HH, HH, (long long)HH * LLs, LLs, LD, (long long)EE * LL, LD, EE);
    // t2 = t @ aw_o + ab_o + x0 ; x = LN(t2) -> x, y fp32 + yh/yl halves
    tcg(th, tl, awoh, awol, t2, nullptr, nullptr, ab_o, x0,
        M, DDIM, DDIM, DDIM, DDIM, DDIM, 1.f, false, 1, 1, 0,0,0,0,0,0);
    ln_kernel<<<M, 128>>>(t2, nullptr, n1g, n1b, x, y, yh, yl);

    // ---- temporal weight preps ----
    transpose_split_kernel<<<dim3(16,16,NBLK), tb>>>(tqw, tqkvwh + 0*DD2, tqkvwl + 0*DD2, DDIM, DDIM, DD2, 3LL*DD2);
    transpose_split_kernel<<<dim3(16,16,NBLK), tb>>>(tkw, tqkvwh + 1*DD2, tqkvwl + 1*DD2, DDIM, DDIM, DD2, 3LL*DD2);
    transpose_split_kernel<<<dim3(16,16,NBLK), tb>>>(tvw, tqkvwh + 2*DD2, tqkvwl + 2*DD2, DDIM, DDIM, DD2, 3LL*DD2);
    transpose_split_kernel<<<dim3(16,16,NBLK), tb>>>(tow, towh, towl, DDIM, DDIM, DD2, DD2);
    transpose_split_kernel<<<dim3(64,16,NBLK), tb>>>(tf1w, f1h, f1l, DDIM, DFF, (long long)DDIM*DFF, (long long)DDIM*DFF);
    transpose_split_kernel<<<dim3(16,64,NBLK), tb>>>(tf2w, f2h, f2l, DFF, DDIM, (long long)DFF*DDIM, (long long)DFF*DDIM);

    // ---- temporal blocks ----
    for (int i = 0; i < NBLK; i++) {
        const __half* Wqkvh = tqkvwh + (long long)i * 3 * DD2;
        const __half* Wqkvl = tqkvwl + (long long)i * 3 * DD2;
        const __half* Woh = towh + (long long)i * DD2;  const __half* Wol = towl + (long long)i * DD2;
        const __half* W1h = f1h + (long long)i * DDIM * DFF;  const __half* W1l = f1l + (long long)i * DDIM * DFF;
        const __half* W2h = f2h + (long long)i * DFF * DDIM;  const __half* W2l = f2l + (long long)i * DFF * DDIM;
        const float* bqkv = tqkvb + i * NQKV;
        const float* bo = tob + i * DDIM;
        const float* b1 = tf1b + i * DFF;  const float* b2 = tf2b + i * DDIM;
        const float* ng = tng + i * DDIM;  const float* nb = tnb + i * DDIM;

        // fused QKV
        tcg(yh, yl, Wqkvh, Wqkvl, nullptr, qkvh, qkvl, bqkv, nullptr,
            M, NQKV, DDIM, DDIM, DDIM, NQKV, 1.f, false, 1, 1, 0,0,0,0,0,0);
        transpose_halves_kernel<<<dim3(16,32,BB), tb>>>(qkvh + 1024, qkvl + 1024, NQKV, QROW,
                                                        vth, vtl, LL, LD);
        // scores (no scaling) -> s fp32
        tcg(qkvh + 0, qkvl + 0, qkvh + 512, qkvl + 512, s, nullptr, nullptr, nullptr, nullptr,
            LL, LL, DDIM, NQKV, NQKV, LL, 1.f, false,
            BB, 1, QROW, 0, QROW, 0, LLs, 0);
        softmax_kernel<<<BB * LL, 256>>>(s, nullptr, sh, sl);
        // probs @ v -> t fp32 (R10 path: fp32 t + permute_split)
        tcg(sh, sl, vth, vtl, t, nullptr, nullptr, nullptr, nullptr,
            LL, DDIM, LL, LL, LL, DDIM, 1.f, false,
            BB, 1, LLs, 0, LD, 0, LD, 0);
        permute_split_kernel<<<(BLD/2 + 255)/256, 256>>>(t, t2h, t2l);
        // y = y + t2 @ Wo + bo  (fp32 y + halves)
        tcg(t2h, t2l, Woh, Wol, y, yh, yl, bo, y,
            M, DDIM, DDIM, DDIM, DDIM, DDIM, 1.f, false, 1, 1, 0,0,0,0,0,0);

        ln_kernel<<<M, 128>>>(y, nullptr, ng, nb, nullptr, nullptr, xnh, xnl);
        tcg(xnh, xnl, W1h, W1l, nullptr, hh, hl, b1, nullptr,
            M, DFF, DDIM, DDIM, DDIM, DFF, 1.f, true, 1, 1, 0,0,0,0,0,0);
        tcg(hh, hl, W2h, W2l, y, yh, yl, b2, y,
            M, DDIM, DFF, DFF, DFF, DDIM, 1.f, false, 1, 1, 0,0,0,0,0,0);
    }

    // ---- final: out = LN(x + y) ----
    ln_kernel<<<M, 128>>>(x, y, n2g, n2b, out_ln, nullptr, nullptr, nullptr);
}

// round 16
// speedup vs baseline: 1.5842x; 1.0192x over previous
#include <cuda_runtime.h>
#include <cuda_fp16.h>
#include <cstdint>

#define BB   8
#define LL   1024
#define DDIM 512
#define HH   8
#define EE   64
#define DFF  2048
#define NBLK 3
#define NQKV 1536
#define BLD  (BB*LL*DDIM)
#define BLQ  (BB*LL*NQKV)
#define BLL  (BB*LL*LL)
#define BHLL (BB*HH*LL*LL)
#define BLDF (BB*LL*DFF)
#define DD2  (DDIM*DDIM)

// ---------------- fp32 scratch ----------------
__device__ float g_t[BLD];
__device__ float g_t2[BLD];
__device__ float g_x[BLD];
__device__ float g_y[BLD];
__device__ float g_s[BLL];
__device__ float g_A[BHLL];
__device__ float g_qkvb[NQKV];
__device__ float g_tqkvb[NBLK*NQKV];
// ---------------- half hi/lo scratch ----------------
__device__ __half g_x0h[BLD],  g_x0l[BLD];
__device__ __half g_qkvh[BLQ], g_qkvl[BLQ];
__device__ __half g_vth[BLD],  g_vtl[BLD];
__device__ __half g_th[BLD],   g_tl[BLD];
__device__ __half g_t2h[BLD],  g_t2l[BLD];
__device__ __half g_yh[BLD],   g_yl[BLD];
__device__ __half g_xnh[BLD],  g_xnl[BLD];
__device__ __half g_hh[BLDF],  g_hl[BLDF];
__device__ __half g_sh[BHLL],  g_sl[BHLL];
__device__ __half g_awqkvh[3*DD2], g_awqkvl[3*DD2];
__device__ __half g_awoh[DD2],     g_awol[DD2];
__device__ __half g_tqkvwh[NBLK*3*DD2], g_tqkvwl[NBLK*3*DD2];
__device__ __half g_towh[NBLK*DD2],     g_towl[NBLK*DD2];
__device__ __half g_f1h[NBLK*DDIM*DFF], g_f1l[NBLK*DDIM*DFF];
__device__ __half g_f2h[NBLK*DFF*DDIM], g_f2l[NBLK*DFF*DDIM];

// ---------------- helpers ----------------
#define SWZ(o) ((uint32_t)(o) ^ ((((uint32_t)(o)) >> 3) & 0x70u))

__device__ __forceinline__ void mma16816(float* d, const uint32_t* a, uint32_t b0, uint32_t b1) {
    asm volatile(
        "mma.sync.aligned.m16n8k16.row.col.f32.f16.f16.f32 "
        "{%0,%1,%2,%3}, {%4,%5,%6,%7}, {%8,%9}, {%0,%1,%2,%3};"
        : "+f"(d[0]), "+f"(d[1]), "+f"(d[2]), "+f"(d[3])
        : "r"(a[0]), "r"(a[1]), "r"(a[2]), "r"(a[3]), "r"(b0), "r"(b1));
}
__device__ __forceinline__ void ldm_x4(uint32_t* r, uint32_t addr) {
    asm volatile("ldmatrix.sync.aligned.m8n8.x4.shared.b16 {%0,%1,%2,%3}, [%4];"
        : "=r"(r[0]), "=r"(r[1]), "=r"(r[2]), "=r"(r[3]) : "r"(addr));
}
__device__ __forceinline__ void cp16(uint32_t dst, const void* src) {
    asm volatile("cp.async.cg.shared.global [%0], [%1], 16;" :: "r"(dst), "l"(src));
}
#define CP_COMMIT() asm volatile("cp.async.commit_group;" ::: "memory")
#define CP_WAIT1()  asm volatile("cp.async.wait_group 1;" ::: "memory")

__device__ __forceinline__ void split2(float x, float y, __half2& h, __half2& l) {
    h = __floats2half2_rn(x, y);
    float2 f = __half22float2(h);
    l = __floats2half2_rn(x - f.x, y - f.y);
}

// ============ fp16 hi/lo split tensor GEMM (3-term, fp32-grade) ============
// C = alpha*A@B^T (+bias)(+res)(relu). A,B hi/lo half arrays, K-major.
// PERM: write C transposed within batch: C[n*LL + m] (temporal permute fused into epilogue).
// CTA 128xBN, 256 threads = 8 warps, warp tile 32x(BN/2). 3-stage pipeline, 2 CTAs/SM.
template<int BN, bool RELU, bool PERM>
__global__ void __launch_bounds__(256, 2) hgemm(
    const __half* __restrict__ Ah, const __half* __restrict__ Al,
    const __half* __restrict__ Bh, const __half* __restrict__ Bl,
    float* __restrict__ C, __half* __restrict__ Ch, __half* __restrict__ Cl,
    const float* __restrict__ bias, const float* __restrict__ res,
    int K, int lda, int ldb, int ldc, float alpha, int inner,
    long long sAo, long long sAi, long long sBo, long long sBi,
    long long sCo, long long sCi)
{
    constexpr int NA   = BN / 16;
    constexpr int ABYT = 128 * 128;
    constexpr int BBYT = BN * 128;
    constexpr int STG  = ABYT + BBYT;
    constexpr int AIT  = 4;
    constexpr int BIT  = BN * 8 / 256;

    extern __shared__ char smch[];
    const uint32_t smb0 = (uint32_t)__cvta_generic_to_shared(smch);

    int z  = blockIdx.z;
    int zo = z / inner;
    int zi = z - zo * inner;
    Ah += zo * sAo + zi * sAi;  Al += zo * sAo + zi * sAi;
    Bh += zo * sBo + zi * sBi;  Bl += zo * sBo + zi * sBi;
    long long coff = zo * sCo + zi * sCi;
    if (C)  C  += coff;
    if (Ch) { Ch += coff; Cl += coff; }
    if (res) res += coff;

    const int tid  = threadIdx.x;
    const int wid  = tid >> 5, lane = tid & 31;
    const int g    = lane >> 2, t4 = lane & 3;
    const int row0 = blockIdx.y * 128, col0 = blockIdx.x * BN;
    const int arow = (wid & 3) * 32;
    const int brow = (wid >> 2) * (BN / 2);

    const int a_r   = arow + (lane & 15);
    const int a_q   = lane >> 4;
    const int b_mat = lane >> 3, b_row = lane & 7;
    const int b_n   = brow + (b_mat >> 1) * 8 + b_row;
    const int b_q   = b_mat & 1;

    float acc[2][NA][4];
    #pragma unroll
    for (int i = 0; i < 2; i++)
        #pragma unroll
        for (int j = 0; j < NA; j++)
            #pragma unroll
            for (int e = 0; e < 4; e++) acc[i][j][e] = 0.f;

    const int NC = K >> 5;

    auto issue_stage = [&](int c, int st) {
        if (c < NC) {
            const int k0 = c << 5;
            uint32_t sA = smb0 + st * STG;
            uint32_t sB = sA + ABYT;
            #pragma unroll
            for (int i = 0; i < AIT; i++) {
                int cb = tid + i * 256;
                int r = cb >> 3, sub = cb & 7;
                const __half* src = (sub < 4 ? Ah : Al) + (size_t)(row0 + r) * lda + k0 + (sub & 3) * 8;
                cp16(sA + SWZ(r * 128 + sub * 16), src);
            }
            #pragma unroll
            for (int i = 0; i < BIT; i++) {
                int cb = tid + i * 256;
                int r = cb >> 3, sub = cb & 7;
                const __half* src = (sub < 4 ? Bh : Bl) + (size_t)(col0 + r) * ldb + k0 + (sub & 3) * 8;
                cp16(sB + SWZ(r * 128 + sub * 16), src);
            }
        }
        CP_COMMIT();
    };

    issue_stage(0, 0);
    issue_stage(1, 1);

    for (int c = 0; c < NC; c++) {
        CP_WAIT1();
        __syncthreads();
        issue_stage(c + 2, (c + 2) % 3);

        const uint32_t sA = smb0 + (c % 3) * STG;
        const uint32_t sB = sA + ABYT;

        #pragma unroll
        for (int ka = 0; ka < 2; ka++) {
            uint32_t ah[2][4], al[2][4];
            #pragma unroll
            for (int ma = 0; ma < 2; ma++) {
                uint32_t off = (uint32_t)(a_r + ma * 16) * 128u + (uint32_t)(ka * 2 + a_q) * 16u;
                ldm_x4(ah[ma], sA + SWZ(off));
                ldm_x4(al[ma], sA + SWZ(off + 64));
            }
            #pragma unroll
            for (int p = 0; p < NA / 2; p++) {
                uint32_t off = (uint32_t)(b_n + p * 16) * 128u + (uint32_t)(ka * 2 + b_q) * 16u;
                uint32_t bh[4], bl[4];
                ldm_x4(bh, sB + SWZ(off));
                ldm_x4(bl, sB + SWZ(off + 64));
                #pragma unroll
                for (int e = 0; e < 2; e++) {
                    #pragma unroll
                    for (int ma = 0; ma < 2; ma++) {
                        float* ac = acc[ma][p * 2 + e];
                        mma16816(ac, ah[ma], bh[e * 2], bh[e * 2 + 1]);
                        mma16816(ac, ah[ma], bl[e * 2], bl[e * 2 + 1]);
                        mma16816(ac, al[ma], bh[e * 2], bh[e * 2 + 1]);
                    }
                }
            }
        }
    }

    // ---- epilogue ----
    #pragma unroll
    for (int ma = 0; ma < 2; ma++) {
        #pragma unroll
        for (int na = 0; na < NA; na++) {
            int r_ = row0 + arow + ma * 16 + g;
            int n_ = col0 + brow + na * 8 + t4 * 2;
            float2 bb = bias ? *(const float2*)&bias[n_] : make_float2(0.f, 0.f);
            #pragma unroll
            for (int hf = 0; hf < 2; hf++) {
                int m = r_ + hf * 8;
                float2 v;
                v.x = acc[ma][na][hf * 2 + 0] * alpha + bb.x;
                v.y = acc[ma][na][hf * 2 + 1] * alpha + bb.y;
                if (res) {
                    float2 rr = *(const float2*)&res[(size_t)m * ldc + n_];
                    v.x += rr.x; v.y += rr.y;
                }
                if (RELU) { v.x = fmaxf(v.x, 0.f); v.y = fmaxf(v.y, 0.f); }
                if (PERM) {
                    // temporal "transpose-reshape" fused: out[n*LL + m]
                    C[(size_t)n_ * LL + m]       = v.x;
                    C[(size_t)(n_ + 1) * LL + m] = v.y;
                } else {
                    if (C) *(float2*)&C[(size_t)m * ldc + n_] = v;
                    if (Ch) {
                        __half2 h2, l2; split2(v.x, v.y, h2, l2);
                        *(__half2*)&Ch[(size_t)m * ldc + n_] = h2;
                        *(__half2*)&Cl[(size_t)m * ldc + n_] = l2;
                    }
                }
            }
        }
    }
}

// ---------------- transpose(+split): out[C,R] halves = split(in[R,C]^T) ----------------
__global__ void transpose_split_kernel(const float* __restrict__ in,
                                       __half* __restrict__ oh, __half* __restrict__ ol,
                                       int R, int C, long long in_bs, long long out_bs)
{
    __shared__ float tile[32][33];
    long long bi = (long long)blockIdx.z * in_bs;
    long long bo = (long long)blockIdx.z * out_bs;
    int c0 = blockIdx.x * 32, r0 = blockIdx.y * 32;
    int tx = threadIdx.x, ty = threadIdx.y;
    #pragma unroll
    for (int j = 0; j < 4; j++)
        tile[ty + j * 8][tx] = in[bi + (long long)(r0 + ty + j * 8) * C + c0 + tx];
    __syncthreads();
    #pragma unroll
    for (int j = 0; j < 4; j++) {
        float v = tile[tx][ty + j * 8];
        __half h = __float2half_rn(v);
        __half l = __float2half_rn(v - __half2float(h));
        long long idx = bo + (long long)(c0 + ty + j * 8) * R + r0 + tx;
        oh[idx] = h; ol[idx] = l;
    }
}

// ---------------- transpose passthrough of pre-split halves ----------------
__global__ void transpose_halves_kernel(const __half* __restrict__ inh, const __half* __restrict__ inl,
                                        int ldin, long long in_bs,
                                        __half* __restrict__ outh, __half* __restrict__ outl,
                                        int ldout, long long out_bs)
{
    __shared__ uint32_t tile[32][33];
    long long bi = (long long)blockIdx.z * in_bs;
    long long bo = (long long)blockIdx.z * out_bs;
    int c0 = blockIdx.x * 32, r0 = blockIdx.y * 32;
    int tx = threadIdx.x, ty = threadIdx.y;
    #pragma unroll
    for (int j = 0; j < 4; j++) {
        long long idx = bi + (long long)(r0 + ty + j * 8) * ldin + c0 + tx;
        uint32_t h = __half_as_ushort(inh[idx]);
        uint32_t l = __half_as_ushort(inl[idx]);
        tile[ty + j * 8][tx] = h | (l << 16);
    }
    __syncthreads();
    #pragma unroll
    for (int j = 0; j < 4; j++) {
        uint32_t u = tile[tx][ty + j * 8];
        long long idx = bo + (long long)(c0 + ty + j * 8) * ldout + r0 + tx;
        outh[idx] = __ushort_as_half((unsigned short)(u & 0xFFFFu));
        outl[idx] = __ushort_as_half((unsigned short)(u >> 16));
    }
}

// ---------------- elementwise split (linear, coalesced) ----------------
__global__ void split_kernel(const float* __restrict__ in,
                             __half* __restrict__ oh, __half* __restrict__ ol, int n4)
{
    int i = blockIdx.x * 256 + threadIdx.x;
    if (i >= n4) return;
    float4 v = ((const float4*)in)[i];
    __half2 h01, l01, h23, l23;
    split2(v.x, v.y, h01, l01);
    split2(v.z, v.w, h23, l23);
    ((__half2*)oh)[i * 2] = h01; ((__half2*)oh)[i * 2 + 1] = h23;
    ((__half2*)ol)[i * 2] = l01; ((__half2*)ol)[i * 2 + 1] = l23;
}

// ---------------- bias packing ----------------
__global__ void bias_pack_kernel(const float* __restrict__ ab_q, const float* __restrict__ ab_k,
                                 const float* __restrict__ ab_v,
                                 const float* __restrict__ tqb, const float* __restrict__ tkb,
                                 const float* __restrict__ tvb,
                                 float* __restrict__ qkvb, float* __restrict__ tqkvb)
{
    int i = blockIdx.x * 256 + threadIdx.x;
    if (i < NQKV) {
        int sec = i >> 9, off = i & 511;
        qkvb[i] = (sec == 0 ? ab_q : sec == 1 ? ab_k : ab_v)[off];
        for (int b = 0; b < NBLK; b++) {
            const float* src = (sec == 0 ? tqb : sec == 1 ? tkb : tvb) + b * DDIM;
            tqkvb[b * NQKV + i] = src[off];
        }
    }
}

// ---------------- softmax rows of 1024; optional fp32 writeback + halves out ----------------
__global__ void softmax_kernel(const float* __restrict__ Pin, float* __restrict__ Pout,
                               __half* __restrict__ Ph, __half* __restrict__ Pl)
{
    long long base = (long long)blockIdx.x * 1024;
    int tid = threadIdx.x;
    __shared__ float red[256];
    float4 vv = *(const float4*)&Pin[base + tid * 4];
    float v[4] = {vv.x, vv.y, vv.z, vv.w};
    float mx = fmaxf(fmaxf(v[0], v[1]), fmaxf(v[2], v[3]));
    red[tid] = mx; __syncthreads();
    for (int s = 128; s > 0; s >>= 1) { if (tid < s) red[tid] = fmaxf(red[tid], red[tid + s]); __syncthreads(); }
    mx = red[0]; __syncthreads();
    float sum = 0.f;
    #pragma unroll
    for (int i = 0; i < 4; i++) { v[i] = __expf(v[i] - mx); sum += v[i]; }
    red[tid] = sum; __syncthreads();
    for (int s = 128; s > 0; s >>= 1) { if (tid < s) red[tid] += red[tid + s]; __syncthreads(); }
    float inv = 1.f / red[0];
    #pragma unroll
    for (int i = 0; i < 4; i++) v[i] *= inv;
    if (Pout) {
        vv.x = v[0]; vv.y = v[1]; vv.z = v[2]; vv.w = v[3];
        *(float4*)&Pout[base + tid * 4] = vv;
    }
    __half2 h01, l01, h23, l23;
    split2(v[0], v[1], h01, l01);
    split2(v[2], v[3], h23, l23);
    *(__half2*)&Ph[base + tid * 4] = h01; *(__half2*)&Ph[base + tid * 4 + 2] = h23;
    *(__half2*)&Pl[base + tid * 4] = l01; *(__half2*)&Pl[base + tid * 4 + 2] = l23;
}

// ---------------- layernorm ----------------
__global__ void ln_kernel(const float* __restrict__ a, const float* __restrict__ b,
                          const float* __restrict__ g, const float* __restrict__ beta,
                          float* __restrict__ out, float* __restrict__ out2,
                          __half* __restrict__ oh, __half* __restrict__ ol)
{
    long long base = (long long)blockIdx.x * 512;
    int tid = threadIdx.x;   // 128
    __shared__ float red[128];
    float4 xv = *(const float4*)&a[base + tid * 4];
    if (b) {
        float4 bv = *(const float4*)&b[base + tid * 4];
        xv.x += bv.x; xv.y += bv.y; xv.z += bv.z; xv.w += bv.w;
    }
    red[tid] = xv.x + xv.y + xv.z + xv.w; __syncthreads();
    for (int s = 64; s > 0; s >>= 1) { if (tid < s) red[tid] += red[tid + s]; __syncthreads(); }
    float mean = red[0] * (1.f / 512.f);
    __syncthreads();
    float d0 = xv.x - mean, d1 = xv.y - mean, d2 = xv.z - mean, d3 = xv.w - mean;
    red[tid] = d0 * d0 + d1 * d1 + d2 * d2 + d3 * d3; __syncthreads();
    for (int s = 64; s > 0; s >>= 1) { if (tid < s) red[tid] += red[tid + s]; __syncthreads(); }
    float rstd = rsqrtf(red[0] * (1.f / 512.f) + 1e-5f);
    float4 gv = *(const float4*)&g[tid * 4];
    float4 bt = *(const float4*)&beta[tid * 4];
    float4 ov;
    ov.x = d0 * rstd * gv.x + bt.x;
    ov.y = d1 * rstd * gv.y + bt.y;
    ov.z = d2 * rstd * gv.z + bt.z;
    ov.w = d3 * rstd * gv.w + bt.w;
    if (out)  *(float4*)&out[base + tid * 4]  = ov;
    if (out2) *(float4*)&out2[base + tid * 4] = ov;
    if (oh) {
        __half2 h01, l01, h23, l23;
        split2(ov.x, ov.y, h01, l01);
        split2(ov.z, ov.w, h23, l23);
        *(__half2*)&oh[base + tid * 4] = h01; *(__half2*)&oh[base + tid * 4 + 2] = h23;
        *(__half2*)&ol[base + tid * 4] = l01; *(__half2*)&ol[base + tid * 4 + 2] = l23;
    }
}

// ---------------- host dispatch ----------------
static void tcg(const __half* Ah, const __half* Al, const __half* Bh, const __half* Bl,
                float* C, __half* Ch, __half* Cl,
                const float* bias, const float* res,
                int M, int N, int K, int lda, int ldb, int ldc,
                float alpha, bool relu, int batch, int inner,
                long long sAo, long long sAi, long long sBo, long long sBi,
                long long sCo, long long sCi)
{
    if (N % 128 == 0) {
        dim3 g(N / 128, M / 128, batch);
        size_t sm = 3ull * (128 + 128) * 128;   // 98304
        if (relu) {
            cudaFuncSetAttribute(hgemm<128, true , false>, cudaFuncAttributeMaxDynamicSharedMemorySize, (int)sm);
            hgemm<128, true , false><<<g, 256, sm>>>(Ah, Al, Bh, Bl, C, Ch, Cl, bias, res, K, lda, ldb, ldc, alpha, inner, sAo, sAi, sBo, sBi, sCo, sCi);
        } else {
            cudaFuncSetAttribute(hgemm<128, false, false>, cudaFuncAttributeMaxDynamicSharedMemorySize, (int)sm);
            hgemm<128, false, false><<<g, 256, sm>>>(Ah, Al, Bh, Bl, C, Ch, Cl, bias, res, K, lda, ldb, ldc, alpha, inner, sAo, sAi, sBo, sBi, sCo, sCi);
        }
    } else { // N == 64
        dim3 g(N / 64, M / 128, batch);
        size_t sm = 3ull * (128 + 64) * 128;    // 73728
        cudaFuncSetAttribute(hgemm<64, false, false>, cudaFuncAttributeMaxDynamicSharedMemorySize, (int)sm);
        hgemm<64, false, false><<<g, 256, sm>>>(Ah, Al, Bh, Bl, C, Ch, Cl, bias, res, K, lda, ldb, ldc, alpha, inner, sAo, sAi, sBo, sBi, sCo, sCi);
    }
}

// permuted-output variant (temporal probs@V only; N multiple of 128)
static void tcg_perm(const __half* Ah, const __half* Al, const __half* Bh, const __half* Bl,
                     float* C,
                     int M, int N, int K, int lda, int ldb,
                     int batch, int inner,
                     long long sAo, long long sAi, long long sBo, long long sBi,
                     long long sCo, long long sCi)
{
    dim3 g(N / 128, M / 128, batch);
    size_t sm = 3ull * (128 + 128) * 128;
    cudaFuncSetAttribute(hgemm<128, false, true>, cudaFuncAttributeMaxDynamicSharedMemorySize, (int)sm);
    hgemm<128, false, true><<<g, 256, sm>>>(Ah, Al, Bh, Bl, C, nullptr, nullptr, nullptr, nullptr,
                                            K, lda, ldb, 0, 1.f, inner, sAo, sAi, sBo, sBi, sCo, sCi);
}

extern "C" void kernel_launch(void* const* d_in, const int* in_sizes, int n_in,
                              void* d_out, int out_size)
{
    const float* x0   = (const float*)d_in[0];
    const float* aw_q = (const float*)d_in[1];   const float* ab_q = (const float*)d_in[2];
    const float* aw_k = (const float*)d_in[3];   const float* ab_k = (const float*)d_in[4];
    const float* aw_v = (const float*)d_in[5];   const float* ab_v = (const float*)d_in[6];
    const float* aw_o = (const float*)d_in[7];   const float* ab_o = (const float*)d_in[8];
    const float* n1g  = (const float*)d_in[9];   const float* n1b  = (const float*)d_in[10];
    const float* n2g  = (const float*)d_in[11];  const float* n2b  = (const float*)d_in[12];
    const float* tqw  = (const float*)d_in[13];  const float* tqb  = (const float*)d_in[14];
    const float* tkw  = (const float*)d_in[15];  const float* tkb  = (const float*)d_in[16];
    const float* tvw  = (const float*)d_in[17];  const float* tvb  = (const float*)d_in[18];
    const float* tow  = (const float*)d_in[19];  const float* tob  = (const float*)d_in[20];
    const float* tf1w = (const float*)d_in[21];  const float* tf1b = (const float*)d_in[22];
    const float* tf2w = (const float*)d_in[23];  const float* tf2b = (const float*)d_in[24];
    const float* tng  = (const float*)d_in[25];  const float* tnb  = (const float*)d_in[26];

    float *t, *t2, *x, *y, *s, *Afb, *qkvb, *tqkvb;
    cudaGetSymbolAddress((void**)&t,    g_t);
    cudaGetSymbolAddress((void**)&t2,   g_t2);
    cudaGetSymbolAddress((void**)&x,    g_x);
    cudaGetSymbolAddress((void**)&y,    g_y);
    cudaGetSymbolAddress((void**)&s,    g_s);
    cudaGetSymbolAddress((void**)&Afb,  g_A);
    cudaGetSymbolAddress((void**)&qkvb, g_qkvb);
    cudaGetSymbolAddress((void**)&tqkvb,g_tqkvb);

    __half *x0h,*x0l,*qkvh,*qkvl,*vth,*vtl,*th,*tl,*t2h,*t2l,*yh,*yl,*xnh,*xnl,*hh,*hl,*sh,*sl;
    __half *awqkvh,*awqkvl,*awoh,*awol,*tqkvwh,*tqkvwl,*towh,*towl,*f1h,*f1l,*f2h,*f2l;
    cudaGetSymbolAddress((void**)&x0h, g_x0h);   cudaGetSymbolAddress((void**)&x0l, g_x0l);
    cudaGetSymbolAddress((void**)&qkvh,g_qkvh);  cudaGetSymbolAddress((void**)&qkvl,g_qkvl);
    cudaGetSymbolAddress((void**)&vth, g_vth);   cudaGetSymbolAddress((void**)&vtl, g_vtl);
    cudaGetSymbolAddress((void**)&th,  g_th);    cudaGetSymbolAddress((void**)&tl,  g_tl);
    cudaGetSymbolAddress((void**)&t2h, g_t2h);   cudaGetSymbolAddress((void**)&t2l, g_t2l);
    cudaGetSymbolAddress((void**)&yh,  g_yh);    cudaGetSymbolAddress((void**)&yl,  g_yl);
    cudaGetSymbolAddress((void**)&xnh, g_xnh);   cudaGetSymbolAddress((void**)&xnl, g_xnl);
    cudaGetSymbolAddress((void**)&hh,  g_hh);    cudaGetSymbolAddress((void**)&hl,  g_hl);
    cudaGetSymbolAddress((void**)&sh,  g_sh);    cudaGetSymbolAddress((void**)&sl,  g_sl);
    cudaGetSymbolAddress((void**)&awqkvh, g_awqkvh); cudaGetSymbolAddress((void**)&awqkvl, g_awqkvl);
    cudaGetSymbolAddress((void**)&awoh, g_awoh); cudaGetSymbolAddress((void**)&awol, g_awol);
    cudaGetSymbolAddress((void**)&tqkvwh, g_tqkvwh); cudaGetSymbolAddress((void**)&tqkvwl, g_tqkvwl);
    cudaGetSymbolAddress((void**)&towh, g_towh); cudaGetSymbolAddress((void**)&towl, g_towl);
    cudaGetSymbolAddress((void**)&f1h, g_f1h);   cudaGetSymbolAddress((void**)&f1l, g_f1l);
    cudaGetSymbolAddress((void**)&f2h, g_f2h);   cudaGetSymbolAddress((void**)&f2l, g_f2l);

    float* out_ln = (float*)d_out;
    float* Ap = (out_size >= (BLD + BHLL)) ? ((float*)d_out + BLD) : Afb;

    const int M = BB * LL;
    const long long LD  = (long long)LL * DDIM;
    const long long LLs = (long long)LL * LL;
    const long long QROW = (long long)LL * NQKV;
    dim3 tb(32, 8);

    // ---- combined biases ----
    bias_pack_kernel<<<(NQKV + 255) / 256, 256>>>(ab_q, ab_k, ab_v, tqb, tkb, tvb, qkvb, tqkvb);

    // ---- preps for outer section ----
    transpose_split_kernel<<<dim3(16,16,1), tb>>>(aw_q, awqkvh + 0*DD2, awqkvl + 0*DD2, DDIM, DDIM, DD2, DD2);
    transpose_split_kernel<<<dim3(16,16,1), tb>>>(aw_k, awqkvh + 1*DD2, awqkvl + 1*DD2, DDIM, DDIM, DD2, DD2);
    transpose_split_kernel<<<dim3(16,16,1), tb>>>(aw_v, awqkvh + 2*DD2, awqkvl + 2*DD2, DDIM, DDIM, DD2, DD2);
    transpose_split_kernel<<<dim3(16,16,1), tb>>>(aw_o, awoh, awol, DDIM, DDIM, DD2, DD2);
    split_kernel<<<(BLD/4 + 255)/256, 256>>>(x0, x0h, x0l, BLD/4);

    // ---- outer MHA: fused QKV (N=1536) ----
    tcg(x0h, x0l, awqkvh, awqkvl, nullptr, qkvh, qkvl, qkvb, nullptr,
        M, NQKV, DDIM, DDIM, DDIM, NQKV, 1.f, false, 1, 1, 0,0,0,0,0,0);
    transpose_halves_kernel<<<dim3(16,32,BB), tb>>>(qkvh + 1024, qkvl + 1024, NQKV, QROW,
                                                    vth, vtl, LL, LD);
    // scores: q_h @ k_h^T / 8 -> Ap fp32
    tcg(qkvh + 0, qkvl + 0, qkvh + 512, qkvl + 512, Ap, nullptr, nullptr, nullptr, nullptr,
        LL, LL, EE, NQKV, NQKV, LL, 0.125f, false,
        BB * HH, HH, QROW, EE, QROW, EE, (long long)HH * LLs, LLs);
    softmax_kernel<<<BB * HH * LL, 256>>>(Ap, Ap, sh, sl);
    // out = A @ v_h -> t halves
    tcg(sh, sl, vth, vtl, nullptr, th, tl, nullptr, nullptr,
        LL, EE, LL, LL, LL, DDIM, 1.f, false,
        BB * HH, HH, (long long)HH * LLs, LLs, LD, (long long)EE * LL, LD, EE);
    // t2 = t @ aw_o + ab_o + x0 ; x = LN(t2)
    tcg(th, tl, awoh, awol, t2, nullptr, nullptr, ab_o, x0,
        M, DDIM, DDIM, DDIM, DDIM, DDIM, 1.f, false, 1, 1, 0,0,0,0,0,0);
    ln_kernel<<<M, 128>>>(t2, nullptr, n1g, n1b, x, y, yh, yl);

    // ---- temporal weight preps ----
    transpose_split_kernel<<<dim3(16,16,NBLK), tb>>>(tqw, tqkvwh + 0*DD2, tqkvwl + 0*DD2, DDIM, DDIM, DD2, 3LL*DD2);
    transpose_split_kernel<<<dim3(16,16,NBLK), tb>>>(tkw, tqkvwh + 1*DD2, tqkvwl + 1*DD2, DDIM, DDIM, DD2, 3LL*DD2);
    transpose_split_kernel<<<dim3(16,16,NBLK), tb>>>(tvw, tqkvwh + 2*DD2, tqkvwl + 2*DD2, DDIM, DDIM, DD2, 3LL*DD2);
    transpose_split_kernel<<<dim3(16,16,NBLK), tb>>>(tow, towh, towl, DDIM, DDIM, DD2, DD2);
    transpose_split_kernel<<<dim3(64,16,NBLK), tb>>>(tf1w, f1h, f1l, DDIM, DFF, (long long)DDIM*DFF, (long long)DDIM*DFF);
    transpose_split_kernel<<<dim3(16,64,NBLK), tb>>>(tf2w, f2h, f2l, DFF, DDIM, (long long)DFF*DDIM, (long long)DFF*DDIM);

    // ---- temporal blocks ----
    for (int i = 0; i < NBLK; i++) {
        const __half* Wqkvh = tqkvwh + (long long)i * 3 * DD2;
        const __half* Wqkvl = tqkvwl + (long long)i * 3 * DD2;
        const __half* Woh = towh + (long long)i * DD2;  const __half* Wol = towl + (long long)i * DD2;
        const __half* W1h = f1h + (long long)i * DDIM * DFF;  const __half* W1l = f1l + (long long)i * DDIM * DFF;
        const __half* W2h = f2h + (long long)i * DFF * DDIM;  const __half* W2l = f2l + (long long)i * DFF * DDIM;
        const float* bqkv = tqkvb + i * NQKV;
        const float* bo = tob + i * DDIM;
        const float* b1 = tf1b + i * DFF;  const float* b2 = tf2b + i * DDIM;
        const float* ng = tng + i * DDIM;  const float* nb = tnb + i * DDIM;

        // fused QKV
        tcg(yh, yl, Wqkvh, Wqkvl, nullptr, qkvh, qkvl, bqkv, nullptr,
            M, NQKV, DDIM, DDIM, DDIM, NQKV, 1.f, false, 1, 1, 0,0,0,0,0,0);
        transpose_halves_kernel<<<dim3(16,32,BB), tb>>>(qkvh + 1024, qkvl + 1024, NQKV, QROW,
                                                        vth, vtl, LL, LD);
        // scores (no scaling) -> s fp32
        tcg(qkvh + 0, qkvl + 0, qkvh + 512, qkvl + 512, s, nullptr, nullptr, nullptr, nullptr,
            LL, LL, DDIM, NQKV, NQKV, LL, 1.f, false,
            BB, 1, QROW, 0, QROW, 0, LLs, 0);
        softmax_kernel<<<BB * LL, 256>>>(s, nullptr, sh, sl);
        // probs @ v -> t fp32 ALREADY PERMUTED (fused transpose-reshape in epilogue)
        tcg_perm(sh, sl, vth, vtl, t,
                 LL, DDIM, LL, LL, LL,
                 BB, 1, LLs, 0, LD, 0, LD, 0);
        // linear split of permuted t -> t2h/t2l (fully coalesced)
        split_kernel<<<(BLD/4 + 255)/256, 256>>>(t, t2h, t2l, BLD/4);
        // y = y + t2 @ Wo + bo  (fp32 y + halves)
        tcg(t2h, t2l, Woh, Wol, y, yh, yl, bo, y,
            M, DDIM, DDIM, DDIM, DDIM, DDIM, 1.f, false, 1, 1, 0,0,0,0,0,0);

        ln_kernel<<<M, 128>>>(y, nullptr, ng, nb, nullptr, nullptr, xnh, xnl);
        tcg(xnh, xnl, W1h, W1l, nullptr, hh, hl, b1, nullptr,
            M, DFF, DDIM, DDIM, DDIM, DFF, 1.f, true, 1, 1, 0,0,0,0,0,0);
        tcg(hh, hl, W2h, W2l, y, yh, yl, b2, y,
            M, DDIM, DFF, DFF, DFF, DDIM, 1.f, false, 1, 1, 0,0,0,0,0,0);
    }

    // ---- final: out = LN(x + y) ----
    ln_kernel<<<M, 128>>>(x, y, n2g, n2b, out_ln, nullptr, nullptr, nullptr);
}